// round 8
// baseline (speedup 1.0000x reference)
#include <cuda_runtime.h>
#include <math.h>

#define NTOK 512
#define DIM 256
#define NH 8
#define HDIM 32
#define HIDN 682

typedef unsigned long long u64;

__device__ __forceinline__ u64 pk2(float lo, float hi) {
    u64 r; asm("mov.b64 %0, {%1,%2};" : "=l"(r) : "f"(lo), "f"(hi)); return r;
}
__device__ __forceinline__ float2 up2(u64 v) {
    float2 f; asm("mov.b64 {%0,%1}, %2;" : "=f"(f.x), "=f"(f.y) : "l"(v)); return f;
}
__device__ __forceinline__ u64 fma2(u64 a, u64 b, u64 c) {
    u64 d; asm("fma.rn.f32x2 %0, %1, %2, %3;" : "=l"(d) : "l"(a), "l"(b), "l"(c)); return d;
}
__device__ __forceinline__ u64 add2(u64 a, u64 b) {
    u64 d; asm("add.rn.f32x2 %0, %1, %2;" : "=l"(d) : "l"(a), "l"(b)); return d;
}
__device__ __forceinline__ float ftanh(float x) {
    float t; asm("tanh.approx.f32 %0, %1;" : "=f"(t) : "f"(x)); return t;
}
__device__ __forceinline__ float fsilu(float x) {
    float h = 0.5f * x;
    return fmaf(h, ftanh(h), h);
}

// ---------------- scratch ----------------
__device__ float g_q[NTOK*DIM];
__device__ float2 g_pb2[DIM*NTOK/2];  // [c][jp] = {-0.5*pb_{2jp}, -0.5*pb_{2jp+1}}
__device__ float2 g_k2[DIM*NTOK/2];   // [c][jp] = {k_{2jp}, k_{2jp+1}}
__device__ float2 g_pvv[NTOK*DIM];    // [j][c] = {-0.5*pv, v}
__device__ float g_rv2T[DIM*DIM];     // [c][o]
__device__ u64   g_rb2d[DIM*NH];      // [c][h] duplicated pairs
__device__ float g_qkvT[DIM*3*DIM];   // [k][o]
__device__ float g_w1T[DIM*HIDN];     // [k][o]
__device__ float g_w2T[DIM*HIDN];
__device__ float g_w3T[HIDN*DIM];     // [o][d]
__device__ float g_scores[NTOK*NH*NTOK]; // [i][h][j]
__device__ float g_resid[NTOK*DIM];
__device__ float g_gate[NTOK*HIDN];

// ---------------- prep: P matrices (prescaled) + rb2 dup ----------------
__global__ void prep_p(const float* __restrict__ coords,
                       const float* __restrict__ rb1_w,
                       const float* __restrict__ rv1_w,
                       const float* __restrict__ rb2_w) {
    int idx = blockIdx.x * 256 + threadIdx.x;   // 512 blocks -> 131072
    {
        int c = idx >> 9, n = idx & 511;        // [c][n]
        float x0 = coords[n*3+0], x1 = coords[n*3+1], x2 = coords[n*3+2];
        float pb = x0*rb1_w[c*3+0] + x1*rb1_w[c*3+1] + x2*rb1_w[c*3+2];
        ((float*)g_pb2)[idx] = -0.5f * pb;
    }
    {
        int n = idx >> 8, c = idx & 255;        // [n][c]
        float x0 = coords[n*3+0], x1 = coords[n*3+1], x2 = coords[n*3+2];
        float pv = x0*rv1_w[c*3+0] + x1*rv1_w[c*3+1] + x2*rv1_w[c*3+2];
        g_pvv[idx].x = -0.5f * pv;
    }
    if (idx < NH*DIM) {
        int h = idx / DIM, c = idx % DIM;
        float r = rb2_w[idx];
        g_rb2d[c*NH + h] = pk2(r, r);
    }
}

// ---------------- tiled transposes ----------------
__global__ void tr_kernel(const float* __restrict__ qkv_w,
                          const float* __restrict__ rv2_w,
                          const float* __restrict__ w1,
                          const float* __restrict__ w2,
                          const float* __restrict__ w3) {
    __shared__ float tile[32][33];
    const float* src; float* dst; int R, C;
    switch (blockIdx.z) {
        case 0: src = qkv_w; dst = g_qkvT; R = 768; C = 256; break;
        case 1: src = rv2_w; dst = g_rv2T; R = 256; C = 256; break;
        case 2: src = w1;    dst = g_w1T;  R = HIDN; C = 256; break;
        case 3: src = w2;    dst = g_w2T;  R = HIDN; C = 256; break;
        default: src = w3;   dst = g_w3T;  R = 256; C = HIDN; break;
    }
    int bx = blockIdx.x * 32, by = blockIdx.y * 32;
    if (bx >= C || by >= R) return;
    int tx = threadIdx.x, ty = threadIdx.y;
    #pragma unroll
    for (int dy = ty; dy < 32; dy += 8) {
        int r = by + dy, cc = bx + tx;
        if (r < R && cc < C) tile[dy][tx] = src[r*C + cc];
    }
    __syncthreads();
    #pragma unroll
    for (int dy = ty; dy < 32; dy += 8) {
        int r = bx + dy, cc = by + tx;   // dst is [C][R]
        if (r < C && cc < R) dst[r*R + cc] = tile[tx][dy];
    }
}

// ---- in-block LayerNorm of 4 rows into xs[c] (float4 over rows) ----
__device__ __forceinline__ void block_ln4(const float* __restrict__ src, int i0,
                                          const float* __restrict__ lnw,
                                          const float* __restrict__ lnb,
                                          float4* xs, float2 (*red2)[4]) {
    int t = threadIdx.x;
    int lane = t & 31, r = t >> 7, wir = (t >> 5) & 3;
    int cc = (t & 127) * 2;
    float2 xv = *(const float2*)&src[(i0+r)*DIM + cc];
    float s1 = xv.x + xv.y;
    float s2 = fmaf(xv.x, xv.x, xv.y*xv.y);
    #pragma unroll
    for (int o = 16; o; o >>= 1) {
        s1 += __shfl_xor_sync(0xffffffffu, s1, o);
        s2 += __shfl_xor_sync(0xffffffffu, s2, o);
    }
    if (lane == 0) red2[r][wir] = make_float2(s1, s2);
    __syncthreads();
    float S1 = red2[r][0].x + red2[r][1].x + red2[r][2].x + red2[r][3].x;
    float S2 = red2[r][0].y + red2[r][1].y + red2[r][2].y + red2[r][3].y;
    float mean = S1 * (1.0f/256.0f);
    float var  = S2 * (1.0f/256.0f) - mean*mean;
    float inv  = rsqrtf(var + 1e-5f);
    float2 wv = *(const float2*)&lnw[cc];
    float2 bv = *(const float2*)&lnb[cc];
    ((float*)&xs[cc])[r]   = (xv.x - mean)*inv*wv.x + bv.x;
    ((float*)&xs[cc+1])[r] = (xv.y - mean)*inv*wv.y + bv.y;
    __syncthreads();
}

// ---------------- QKV (LN1 fused): 4 rows, 256-col chunk, 2 cols/thread, k-split 4 ----------------
__global__ __launch_bounds__(512) void qkv_kernel(const float* __restrict__ x,
                                                  const float* __restrict__ ln1_w,
                                                  const float* __restrict__ ln1_b,
                                                  const float* __restrict__ qkv_b) {
    __shared__ float4 xs[DIM];
    __shared__ float2 red2[4][4];
    __shared__ u64 part[128][3][4];
    int t = threadIdx.x;
    int i0 = blockIdx.x * 4, chunk = blockIdx.y;
    block_ln4(x, i0, ln1_w, ln1_b, xs, red2);

    int p = t & 127, kh = t >> 7;
    int ob = chunk*256 + p*2;
    u64 a0 = 0, a1 = 0, b0 = 0, b1 = 0;
    int kbeg = kh * 64;
    #pragma unroll 4
    for (int kk = 0; kk < 64; kk++) {
        int k = kbeg + kk;
        float2 w2 = *(const float2*)&g_qkvT[k*768 + ob];
        ulonglong2 xv = *(const ulonglong2*)&xs[k];
        u64 w0 = pk2(w2.x, w2.x), w1 = pk2(w2.y, w2.y);
        a0 = fma2(xv.x, w0, a0); a1 = fma2(xv.y, w0, a1);
        b0 = fma2(xv.x, w1, b0); b1 = fma2(xv.y, w1, b1);
    }
    if (kh) { part[p][kh-1][0]=a0; part[p][kh-1][1]=a1; part[p][kh-1][2]=b0; part[p][kh-1][3]=b1; }
    __syncthreads();
    if (kh == 0) {
        #pragma unroll
        for (int m = 0; m < 3; m++) {
            a0 = add2(a0, part[p][m][0]); a1 = add2(a1, part[p][m][1]);
            b0 = add2(b0, part[p][m][2]); b1 = add2(b1, part[p][m][3]);
        }
        float2 bb = *(const float2*)&qkv_b[ob];
        float2 A = up2(a0), B = up2(a1), C = up2(b0), D = up2(b1);
        float r0[4] = { A.x+bb.x, A.y+bb.x, B.x+bb.x, B.y+bb.x };
        float r1[4] = { C.x+bb.y, C.y+bb.y, D.x+bb.y, D.y+bb.y };
        if (chunk == 0) {
            #pragma unroll
            for (int rr = 0; rr < 4; rr++) {
                g_q[(i0+rr)*DIM + ob]   = r0[rr];
                g_q[(i0+rr)*DIM + ob+1] = r1[rr];
            }
        } else if (chunk == 1) {
            int c0 = ob - 256, jp = i0 >> 1;
            g_k2[c0*256 + jp]       = make_float2(r0[0], r0[1]);
            g_k2[c0*256 + jp + 1]   = make_float2(r0[2], r0[3]);
            g_k2[(c0+1)*256 + jp]   = make_float2(r1[0], r1[1]);
            g_k2[(c0+1)*256 + jp+1] = make_float2(r1[2], r1[3]);
        } else {
            int c0 = ob - 512;
            #pragma unroll
            for (int rr = 0; rr < 4; rr++) {
                ((float*)g_pvv)[((i0+rr)*DIM + c0)*2 + 1]   = r0[rr];
                ((float*)g_pvv)[((i0+rr)*DIM + c0+1)*2 + 1] = r1[rr];
            }
        }
    }
}

// ---------------- scores: 2 i x 512 j per block, j-pair per thread ----------------
__global__ __launch_bounds__(256, 4) void scores_kernel(const float* __restrict__ rb1_b,
                                                        const float* __restrict__ rb2_b) {
    __shared__ ulonglong2 phq[DIM][2];  // [c] = {ph0_dup, ph1_dup}, {q0s_dup, q1s_dup}
    __shared__ u64 rbs[DIM*NH];         // 16KB duplicated rb2
    int i0 = blockIdx.x * 2;
    int t = threadIdx.x;
    const float sc = 0.17677669529663687f; // 1/sqrt(32)

    {
        float bh = 0.5f * rb1_b[t];
        float2 pbi = g_pb2[t*256 + (i0 >> 1)];  // {-½pb_i0, -½pb_i1}
        float p0 = bh - pbi.x, p1 = bh - pbi.y;
        float q0 = g_q[i0*DIM + t] * sc, q1 = g_q[(i0+1)*DIM + t] * sc;
        phq[t][0] = make_ulonglong2(pk2(p0, p0), pk2(p1, p1));
        phq[t][1] = make_ulonglong2(pk2(q0, q0), pk2(q1, q1));
    }
    #pragma unroll
    for (int m = 0; m < 8; m++) rbs[m*256 + t] = g_rb2d[m*256 + t];
    __syncthreads();

    const u64* pbp = (const u64*)g_pb2 + t;
    const u64* kp  = (const u64*)g_k2 + t;

    u64 accb0[8] = {}, accb1[8] = {};
    #pragma unroll
    for (int h = 0; h < NH; h++) {
        u64 s0 = 0, s1 = 0;
        #pragma unroll 4
        for (int c32 = 0; c32 < 32; c32++) {
            int c = h*32 + c32;
            u64 pb2 = pbp[c*256];            // {-½pb_j0, -½pb_j1}
            u64 k2  = kp[c*256];             // {k_j0, k_j1}
            ulonglong2 pq0 = phq[c][0];
            ulonglong2 pq1 = phq[c][1];
            u64 h20 = add2(pq0.x, pb2);      // silu half-arg, i0 vs j-pair
            u64 h21 = add2(pq0.y, pb2);      // i1 vs j-pair
            float2 f0 = up2(h20), f1 = up2(h21);
            u64 t20 = pk2(ftanh(f0.x), ftanh(f0.y));
            u64 t21 = pk2(ftanh(f1.x), ftanh(f1.y));
            u64 hb0 = fma2(h20, t20, h20);   // silu, j-packed, i0
            u64 hb1 = fma2(h21, t21, h21);   // i1
            ulonglong2 rA = *(const ulonglong2*)&rbs[c*8 + 0];
            ulonglong2 rB = *(const ulonglong2*)&rbs[c*8 + 2];
            ulonglong2 rC = *(const ulonglong2*)&rbs[c*8 + 4];
            ulonglong2 rD = *(const ulonglong2*)&rbs[c*8 + 6];
            accb0[0] = fma2(rA.x, hb0, accb0[0]); accb1[0] = fma2(rA.x, hb1, accb1[0]);
            accb0[1] = fma2(rA.y, hb0, accb0[1]); accb1[1] = fma2(rA.y, hb1, accb1[1]);
            accb0[2] = fma2(rB.x, hb0, accb0[2]); accb1[2] = fma2(rB.x, hb1, accb1[2]);
            accb0[3] = fma2(rB.y, hb0, accb0[3]); accb1[3] = fma2(rB.y, hb1, accb1[3]);
            accb0[4] = fma2(rC.x, hb0, accb0[4]); accb1[4] = fma2(rC.x, hb1, accb1[4]);
            accb0[5] = fma2(rC.y, hb0, accb0[5]); accb1[5] = fma2(rC.y, hb1, accb1[5]);
            accb0[6] = fma2(rD.x, hb0, accb0[6]); accb1[6] = fma2(rD.x, hb1, accb1[6]);
            accb0[7] = fma2(rD.y, hb0, accb0[7]); accb1[7] = fma2(rD.y, hb1, accb1[7]);
            s0 = fma2(pq1.x, k2, s0);
            s1 = fma2(pq1.y, k2, s1);
        }
        accb0[h] = add2(accb0[h], s0);   // fold scaled qk for head h
        accb1[h] = add2(accb1[h], s1);
    }
    #pragma unroll
    for (int h = 0; h < NH; h++) {
        float rbb = rb2_b[h];
        float2 v0 = up2(accb0[h]);
        float2 v1 = up2(accb1[h]);
        *(float2*)&g_scores[(i0*NH + h)*NTOK + 2*t]     = make_float2(v0.x + rbb, v0.y + rbb);
        *(float2*)&g_scores[((i0+1)*NH + h)*NTOK + 2*t] = make_float2(v1.x + rbb, v1.y + rbb);
    }
}

// ---------------- attention ----------------
__global__ __launch_bounds__(256, 4) void attn_kernel(const float* __restrict__ x,
                                                      const float* __restrict__ rv1_b,
                                                      const float* __restrict__ rv2_b) {
    __shared__ float wT[NTOK*12];
    __shared__ float whid[NH*DIM];
    __shared__ float sinv[NH];
    int i = blockIdx.x, t = threadIdx.x;
    int wid = t >> 5, lane = t & 31;

    {
        const float* row = g_scores + (i*NH + wid)*NTOK;
        float m = -1e30f;
        for (int jj = lane; jj < NTOK; jj += 32) m = fmaxf(m, row[jj]);
        #pragma unroll
        for (int o = 16; o; o >>= 1) m = fmaxf(m, __shfl_xor_sync(0xffffffffu, m, o));
        float s = 0.f;
        for (int jj = lane; jj < NTOK; jj += 32) {
            float e = __expf(row[jj] - m);
            wT[jj*12 + wid] = e;
            s += e;
        }
        #pragma unroll
        for (int o = 16; o; o >>= 1) s += __shfl_xor_sync(0xffffffffu, s, o);
        if (lane == 0) sinv[wid] = __fdividef(1.0f, s);
    }
    __syncthreads();

    float pvih = 0.5f*rv1_b[t] - g_pvv[i*DIM + t].x;
    int hs = t >> 5;
    u64 accW[4] = {};
    float accC = 0.f;
    #pragma unroll 2
    for (int j = 0; j < NTOK; j++) {
        float2 pv = g_pvv[j*DIM + t];
        ulonglong2 wA = *(const ulonglong2*)&wT[j*12];
        ulonglong2 wB = *(const ulonglong2*)&wT[j*12 + 4];
        float hin = pvih + pv.x;
        float hv = fmaf(hin, ftanh(hin), hin);
        u64 hh = pk2(hv, hv);
        accW[0] = fma2(hh, wA.x, accW[0]); accW[1] = fma2(hh, wA.y, accW[1]);
        accW[2] = fma2(hh, wB.x, accW[2]); accW[3] = fma2(hh, wB.y, accW[3]);
        accC += wT[j*12 + hs] * pv.y;
    }
    #pragma unroll
    for (int hp = 0; hp < 4; hp++) {
        float2 v = up2(accW[hp]);
        whid[(2*hp)*DIM + t]   = v.x * sinv[2*hp];
        whid[(2*hp+1)*DIM + t] = v.y * sinv[2*hp+1];
    }
    accC *= sinv[hs];
    __syncthreads();

    float accP = 0.f;
    #pragma unroll 4
    for (int c = 0; c < DIM; c++)
        accP += whid[hs*DIM + c] * g_rv2T[c*DIM + t];

    g_resid[i*DIM + t] = x[i*DIM + t] + accC + accP + rv2_b[t];
}

// ---------------- FFN up (LN2 fused): 4 rows, 2 cols/thread, k-split 4 ----------------
__global__ __launch_bounds__(512) void ffn1_kernel(const float* __restrict__ ln2_w,
                                                   const float* __restrict__ ln2_b,
                                                   const float* __restrict__ b1,
                                                   const float* __restrict__ b2) {
    __shared__ float4 xs[DIM];
    __shared__ float2 red2[4][4];
    __shared__ u64 parta[128][3][4];
    __shared__ u64 partc[128][3][4];
    int t = threadIdx.x;
    int i0 = blockIdx.x * 4, chunk = blockIdx.y;
    block_ln4(g_resid, i0, ln2_w, ln2_b, xs, red2);

    int p = t & 127, kh = t >> 7;
    int o = chunk*256 + p*2;
    int ocl = (o <= HIDN-2) ? o : (HIDN-2);
    u64 a0=0, a1=0, a2=0, a3=0, c0=0, c1=0, c2=0, c3=0;
    int kbeg = kh * 64;
    #pragma unroll 4
    for (int kk = 0; kk < 64; kk++) {
        int k = kbeg + kk;
        float2 u2 = *(const float2*)&g_w1T[k*HIDN + ocl];
        float2 v2 = *(const float2*)&g_w2T[k*HIDN + ocl];
        ulonglong2 xv = *(const ulonglong2*)&xs[k];
        u64 u0 = pk2(u2.x,u2.x), u1 = pk2(u2.y,u2.y);
        u64 v0 = pk2(v2.x,v2.x), v1 = pk2(v2.y,v2.y);
        a0 = fma2(xv.x,u0,a0); a1 = fma2(xv.y,u0,a1);
        a2 = fma2(xv.x,u1,a2); a3 = fma2(xv.y,u1,a3);
        c0 = fma2(xv.x,v0,c0); c1 = fma2(xv.y,v0,c1);
        c2 = fma2(xv.x,v1,c2); c3 = fma2(xv.y,v1,c3);
    }
    if (kh) {
        parta[p][kh-1][0]=a0; parta[p][kh-1][1]=a1; parta[p][kh-1][2]=a2; parta[p][kh-1][3]=a3;
        partc[p][kh-1][0]=c0; partc[p][kh-1][1]=c1; partc[p][kh-1][2]=c2; partc[p][kh-1][3]=c3;
    }
    __syncthreads();
    if (kh == 0 && o < HIDN) {
        #pragma unroll
        for (int m = 0; m < 3; m++) {
            a0 = add2(a0, parta[p][m][0]); a1 = add2(a1, parta[p][m][1]);
            a2 = add2(a2, parta[p][m][2]); a3 = add2(a3, parta[p][m][3]);
            c0 = add2(c0, partc[p][m][0]); c1 = add2(c1, partc[p][m][1]);
            c2 = add2(c2, partc[p][m][2]); c3 = add2(c3, partc[p][m][3]);
        }
        float2 A0 = up2(a0), A1 = up2(a1), A2 = up2(a2), A3 = up2(a3);
        float2 C0 = up2(c0), C1 = up2(c1), C2 = up2(c2), C3 = up2(c3);
        float bb10 = b1[o], bb11 = b1[o+1], bb20 = b2[o], bb21 = b2[o+1];
        g_gate[(i0+0)*HIDN + o]   = fsilu(A0.x + bb10) * (C0.x + bb20);
        g_gate[(i0+1)*HIDN + o]   = fsilu(A0.y + bb10) * (C0.y + bb20);
        g_gate[(i0+2)*HIDN + o]   = fsilu(A1.x + bb10) * (C1.x + bb20);
        g_gate[(i0+3)*HIDN + o]   = fsilu(A1.y + bb10) * (C1.y + bb20);
        g_gate[(i0+0)*HIDN + o+1] = fsilu(A2.x + bb11) * (C2.x + bb21);
        g_gate[(i0+1)*HIDN + o+1] = fsilu(A2.y + bb11) * (C2.y + bb21);
        g_gate[(i0+2)*HIDN + o+1] = fsilu(A3.x + bb11) * (C3.x + bb21);
        g_gate[(i0+3)*HIDN + o+1] = fsilu(A3.y + bb11) * (C3.y + bb21);
    }
}

// ---------------- FFN down + residual: 2 rows, 2 cols/thread, o-split 4 ----------------
__global__ __launch_bounds__(512) void ffn2_kernel(const float* __restrict__ b3,
                                                   float* __restrict__ out) {
    __shared__ float2 gs[HIDN];
    __shared__ u64 part[128][3][2];
    int i0 = blockIdx.x * 2, t = threadIdx.x;
    int p = t & 127, oh = t >> 7;
    for (int idx = t; idx < HIDN; idx += 512)
        gs[idx] = make_float2(g_gate[i0*HIDN + idx], g_gate[(i0+1)*HIDN + idx]);
    __syncthreads();
    const int obeg[5] = {0, 171, 342, 512, 682};
    int os = obeg[oh], oe = obeg[oh+1];
    int d = p*2;
    u64 acc0 = 0, acc1 = 0;
    for (int o = os; o < oe; o++) {
        float2 w = *(const float2*)&g_w3T[o*DIM + d];
        u64 g2 = *(const u64*)&gs[o];
        acc0 = fma2(g2, pk2(w.x, w.x), acc0);
        acc1 = fma2(g2, pk2(w.y, w.y), acc1);
    }
    if (oh) { part[p][oh-1][0] = acc0; part[p][oh-1][1] = acc1; }
    __syncthreads();
    if (oh == 0) {
        #pragma unroll
        for (int m = 0; m < 3; m++) {
            acc0 = add2(acc0, part[p][m][0]);
            acc1 = add2(acc1, part[p][m][1]);
        }
        float2 A = up2(acc0), B = up2(acc1);
        float2 bb = *(const float2*)&b3[d];
        out[i0*DIM + d]       = g_resid[i0*DIM + d]       + A.x + bb.x;
        out[(i0+1)*DIM + d]   = g_resid[(i0+1)*DIM + d]   + A.y + bb.x;
        out[i0*DIM + d+1]     = g_resid[i0*DIM + d+1]     + B.x + bb.y;
        out[(i0+1)*DIM + d+1] = g_resid[(i0+1)*DIM + d+1] + B.y + bb.y;
    }
}

// ---------------- launch ----------------
extern "C" void kernel_launch(void* const* d_in, const int* in_sizes, int n_in,
                              void* d_out, int out_size) {
    const float* x      = (const float*)d_in[0];
    const float* coords = (const float*)d_in[1];
    const float* ln1_w  = (const float*)d_in[2];
    const float* ln1_b  = (const float*)d_in[3];
    const float* ln2_w  = (const float*)d_in[4];
    const float* ln2_b  = (const float*)d_in[5];
    const float* qkv_w  = (const float*)d_in[6];
    const float* qkv_b  = (const float*)d_in[7];
    const float* rb1_w  = (const float*)d_in[8];
    const float* rb1_b  = (const float*)d_in[9];
    const float* rb2_w  = (const float*)d_in[10];
    const float* rb2_b  = (const float*)d_in[11];
    const float* rv1_w  = (const float*)d_in[12];
    const float* rv1_b  = (const float*)d_in[13];
    const float* rv2_w  = (const float*)d_in[14];
    const float* rv2_b  = (const float*)d_in[15];
    const float* w1     = (const float*)d_in[16];
    const float* b1     = (const float*)d_in[17];
    const float* w2     = (const float*)d_in[18];
    const float* b2     = (const float*)d_in[19];
    const float* w3     = (const float*)d_in[20];
    const float* b3     = (const float*)d_in[21];
    float* out = (float*)d_out;

    prep_p<<<512, 256>>>(coords, rb1_w, rv1_w, rb2_w);
    tr_kernel<<<dim3(22, 24, 5), dim3(32, 8)>>>(qkv_w, rv2_w, w1, w2, w3);
    qkv_kernel<<<dim3(128, 3), 512>>>(x, ln1_w, ln1_b, qkv_b);
    scores_kernel<<<256, 256>>>(rb1_b, rb2_b);
    attn_kernel<<<NTOK, 256>>>(x, rv1_b, rv2_b);
    ffn1_kernel<<<dim3(128, 3), 512>>>(ln2_w, ln2_b, b1, b2);
    ffn2_kernel<<<256, 512>>>(b3, out);
}

// round 9
// speedup vs baseline: 1.0929x; 1.0929x over previous
#include <cuda_runtime.h>
#include <math.h>

#define NTOK 512
#define DIM 256
#define NH 8
#define HDIM 32
#define HIDN 682

typedef unsigned long long u64;

__device__ __forceinline__ u64 pk2(float lo, float hi) {
    u64 r; asm("mov.b64 %0, {%1,%2};" : "=l"(r) : "f"(lo), "f"(hi)); return r;
}
__device__ __forceinline__ float2 up2(u64 v) {
    float2 f; asm("mov.b64 {%0,%1}, %2;" : "=f"(f.x), "=f"(f.y) : "l"(v)); return f;
}
__device__ __forceinline__ u64 fma2(u64 a, u64 b, u64 c) {
    u64 d; asm("fma.rn.f32x2 %0, %1, %2, %3;" : "=l"(d) : "l"(a), "l"(b), "l"(c)); return d;
}
__device__ __forceinline__ u64 add2(u64 a, u64 b) {
    u64 d; asm("add.rn.f32x2 %0, %1, %2;" : "=l"(d) : "l"(a), "l"(b)); return d;
}
__device__ __forceinline__ float ftanh(float x) {
    float t; asm("tanh.approx.f32 %0, %1;" : "=f"(t) : "f"(x)); return t;
}
__device__ __forceinline__ float fsilu(float x) {
    float h = 0.5f * x;
    return fmaf(h, ftanh(h), h);
}

// ---------------- scratch ----------------
__device__ float g_q[NTOK*DIM];
__device__ float2 g_pb2[DIM*NTOK/2];  // [c][jp] = {-0.5*pb_{2jp}, -0.5*pb_{2jp+1}}
__device__ float2 g_k2[DIM*NTOK/2];   // [c][jp] = {k_{2jp}, k_{2jp+1}}
__device__ float2 g_pvv[NTOK*DIM];    // [j][c] = {-0.5*pv, v}
__device__ float g_rv2T[DIM*DIM];     // [c][o]
__device__ u64   g_rb2d[DIM*NH];      // [c][h] duplicated pairs
__device__ float g_qkvT[DIM*3*DIM];   // [k][o]
__device__ float g_w1T[DIM*HIDN];     // [k][o]
__device__ float g_w2T[DIM*HIDN];
__device__ float g_w3T[HIDN*DIM];     // [o][d]
__device__ float g_scores[NTOK*NH*NTOK]; // [i][h][j]
__device__ float g_resid[NTOK*DIM];
__device__ float g_gate[NTOK*HIDN];

// ---------------- prep: P matrices (prescaled) + rb2 dup ----------------
__global__ void prep_p(const float* __restrict__ coords,
                       const float* __restrict__ rb1_w,
                       const float* __restrict__ rv1_w,
                       const float* __restrict__ rb2_w) {
    int idx = blockIdx.x * 256 + threadIdx.x;   // 512 blocks -> 131072
    {
        int c = idx >> 9, n = idx & 511;        // [c][n]
        float x0 = coords[n*3+0], x1 = coords[n*3+1], x2 = coords[n*3+2];
        float pb = x0*rb1_w[c*3+0] + x1*rb1_w[c*3+1] + x2*rb1_w[c*3+2];
        ((float*)g_pb2)[idx] = -0.5f * pb;
    }
    {
        int n = idx >> 8, c = idx & 255;        // [n][c]
        float x0 = coords[n*3+0], x1 = coords[n*3+1], x2 = coords[n*3+2];
        float pv = x0*rv1_w[c*3+0] + x1*rv1_w[c*3+1] + x2*rv1_w[c*3+2];
        g_pvv[idx].x = -0.5f * pv;
    }
    if (idx < NH*DIM) {
        int h = idx / DIM, c = idx % DIM;
        float r = rb2_w[idx];
        g_rb2d[c*NH + h] = pk2(r, r);
    }
}

// ---------------- tiled transposes ----------------
__global__ void tr_kernel(const float* __restrict__ qkv_w,
                          const float* __restrict__ rv2_w,
                          const float* __restrict__ w1,
                          const float* __restrict__ w2,
                          const float* __restrict__ w3) {
    __shared__ float tile[32][33];
    const float* src; float* dst; int R, C;
    switch (blockIdx.z) {
        case 0: src = qkv_w; dst = g_qkvT; R = 768; C = 256; break;
        case 1: src = rv2_w; dst = g_rv2T; R = 256; C = 256; break;
        case 2: src = w1;    dst = g_w1T;  R = HIDN; C = 256; break;
        case 3: src = w2;    dst = g_w2T;  R = HIDN; C = 256; break;
        default: src = w3;   dst = g_w3T;  R = 256; C = HIDN; break;
    }
    int bx = blockIdx.x * 32, by = blockIdx.y * 32;
    if (bx >= C || by >= R) return;
    int tx = threadIdx.x, ty = threadIdx.y;
    #pragma unroll
    for (int dy = ty; dy < 32; dy += 8) {
        int r = by + dy, cc = bx + tx;
        if (r < R && cc < C) tile[dy][tx] = src[r*C + cc];
    }
    __syncthreads();
    #pragma unroll
    for (int dy = ty; dy < 32; dy += 8) {
        int r = bx + dy, cc = by + tx;   // dst is [C][R]
        if (r < C && cc < R) dst[r*R + cc] = tile[tx][dy];
    }
}

// ---- in-block LayerNorm of 4 rows into xs[c] (float4 over rows) ----
__device__ __forceinline__ void block_ln4(const float* __restrict__ src, int i0,
                                          const float* __restrict__ lnw,
                                          const float* __restrict__ lnb,
                                          float4* xs, float2 (*red2)[4]) {
    int t = threadIdx.x;
    int lane = t & 31, r = t >> 7, wir = (t >> 5) & 3;
    int cc = (t & 127) * 2;
    float2 xv = *(const float2*)&src[(i0+r)*DIM + cc];
    float s1 = xv.x + xv.y;
    float s2 = fmaf(xv.x, xv.x, xv.y*xv.y);
    #pragma unroll
    for (int o = 16; o; o >>= 1) {
        s1 += __shfl_xor_sync(0xffffffffu, s1, o);
        s2 += __shfl_xor_sync(0xffffffffu, s2, o);
    }
    if (lane == 0) red2[r][wir] = make_float2(s1, s2);
    __syncthreads();
    float S1 = red2[r][0].x + red2[r][1].x + red2[r][2].x + red2[r][3].x;
    float S2 = red2[r][0].y + red2[r][1].y + red2[r][2].y + red2[r][3].y;
    float mean = S1 * (1.0f/256.0f);
    float var  = S2 * (1.0f/256.0f) - mean*mean;
    float inv  = rsqrtf(var + 1e-5f);
    float2 wv = *(const float2*)&lnw[cc];
    float2 bv = *(const float2*)&lnb[cc];
    ((float*)&xs[cc])[r]   = (xv.x - mean)*inv*wv.x + bv.x;
    ((float*)&xs[cc+1])[r] = (xv.y - mean)*inv*wv.y + bv.y;
    __syncthreads();
}

// ---------------- QKV (LN1 fused): 4 rows, 256-col chunk, 2 cols/thread, k-split 4 ----------------
__global__ __launch_bounds__(512) void qkv_kernel(const float* __restrict__ x,
                                                  const float* __restrict__ ln1_w,
                                                  const float* __restrict__ ln1_b,
                                                  const float* __restrict__ qkv_b) {
    __shared__ float4 xs[DIM];
    __shared__ float2 red2[4][4];
    __shared__ u64 part[128][3][4];
    int t = threadIdx.x;
    int i0 = blockIdx.x * 4, chunk = blockIdx.y;
    block_ln4(x, i0, ln1_w, ln1_b, xs, red2);

    int p = t & 127, kh = t >> 7;
    int ob = chunk*256 + p*2;
    u64 a0 = 0, a1 = 0, b0 = 0, b1 = 0;
    int kbeg = kh * 64;
    #pragma unroll 4
    for (int kk = 0; kk < 64; kk++) {
        int k = kbeg + kk;
        float2 w2 = *(const float2*)&g_qkvT[k*768 + ob];
        ulonglong2 xv = *(const ulonglong2*)&xs[k];
        u64 w0 = pk2(w2.x, w2.x), w1 = pk2(w2.y, w2.y);
        a0 = fma2(xv.x, w0, a0); a1 = fma2(xv.y, w0, a1);
        b0 = fma2(xv.x, w1, b0); b1 = fma2(xv.y, w1, b1);
    }
    if (kh) { part[p][kh-1][0]=a0; part[p][kh-1][1]=a1; part[p][kh-1][2]=b0; part[p][kh-1][3]=b1; }
    __syncthreads();
    if (kh == 0) {
        #pragma unroll
        for (int m = 0; m < 3; m++) {
            a0 = add2(a0, part[p][m][0]); a1 = add2(a1, part[p][m][1]);
            b0 = add2(b0, part[p][m][2]); b1 = add2(b1, part[p][m][3]);
        }
        float2 bb = *(const float2*)&qkv_b[ob];
        float2 A = up2(a0), B = up2(a1), C = up2(b0), D = up2(b1);
        float r0[4] = { A.x+bb.x, A.y+bb.x, B.x+bb.x, B.y+bb.x };
        float r1[4] = { C.x+bb.y, C.y+bb.y, D.x+bb.y, D.y+bb.y };
        if (chunk == 0) {
            #pragma unroll
            for (int rr = 0; rr < 4; rr++) {
                g_q[(i0+rr)*DIM + ob]   = r0[rr];
                g_q[(i0+rr)*DIM + ob+1] = r1[rr];
            }
        } else if (chunk == 1) {
            int c0 = ob - 256, jp = i0 >> 1;
            g_k2[c0*256 + jp]       = make_float2(r0[0], r0[1]);
            g_k2[c0*256 + jp + 1]   = make_float2(r0[2], r0[3]);
            g_k2[(c0+1)*256 + jp]   = make_float2(r1[0], r1[1]);
            g_k2[(c0+1)*256 + jp+1] = make_float2(r1[2], r1[3]);
        } else {
            int c0 = ob - 512;
            #pragma unroll
            for (int rr = 0; rr < 4; rr++) {
                ((float*)g_pvv)[((i0+rr)*DIM + c0)*2 + 1]   = r0[rr];
                ((float*)g_pvv)[((i0+rr)*DIM + c0+1)*2 + 1] = r1[rr];
            }
        }
    }
}

// ---------------- scores: 2 i x 512 j per block, j-pair x c-half per thread ----------------
__global__ __launch_bounds__(512, 2) void scores_kernel(const float* __restrict__ rb1_b,
                                                        const float* __restrict__ rb2_b) {
    __shared__ ulonglong2 phq[DIM][2];  // [c] = {ph0_dup, ph1_dup}, {q0s_dup, q1s_dup}
    __shared__ u64 rbs[DIM*NH];         // 16KB duplicated rb2
    __shared__ u64 parts[16][256];      // [m][jp] partials from upper c-half
    int i0 = blockIdx.x * 2;
    int t = threadIdx.x;
    int jp = t & 255, ch = t >> 8;      // ch: c-half (warp-uniform)
    const float sc = 0.17677669529663687f;

    if (t < 256) {
        float bh = 0.5f * rb1_b[t];
        float2 pbi = g_pb2[t*256 + (i0 >> 1)];  // {-½pb_i0, -½pb_i1}
        float p0 = bh - pbi.x, p1 = bh - pbi.y;
        float q0 = g_q[i0*DIM + t] * sc, q1 = g_q[(i0+1)*DIM + t] * sc;
        phq[t][0] = make_ulonglong2(pk2(p0, p0), pk2(p1, p1));
        phq[t][1] = make_ulonglong2(pk2(q0, q0), pk2(q1, q1));
    }
    #pragma unroll
    for (int m = 0; m < 4; m++) rbs[m*512 + t] = g_rb2d[m*512 + t];
    __syncthreads();

    const u64* pbp = (const u64*)g_pb2 + jp;
    const u64* kp  = (const u64*)g_k2 + jp;
    int cbase = ch * 128;

    u64 accb0[8] = {}, accb1[8] = {};
    #pragma unroll
    for (int hs = 0; hs < 4; hs++) {
        u64 s0 = 0, s1 = 0;
        #pragma unroll 4
        for (int c32 = 0; c32 < 32; c32++) {
            int c = cbase + hs*32 + c32;
            u64 pb2v = pbp[c*256];           // {-½pb_j0, -½pb_j1}
            u64 k2v  = kp[c*256];            // {k_j0, k_j1}
            ulonglong2 pq0 = phq[c][0];
            ulonglong2 pq1 = phq[c][1];
            u64 h20 = add2(pq0.x, pb2v);     // silu half-arg, i0 vs j-pair
            u64 h21 = add2(pq0.y, pb2v);     // i1 vs j-pair
            float2 f0 = up2(h20), f1 = up2(h21);
            u64 t20 = pk2(ftanh(f0.x), ftanh(f0.y));
            u64 t21 = pk2(ftanh(f1.x), ftanh(f1.y));
            u64 hb0 = fma2(h20, t20, h20);   // silu, j-packed, i0
            u64 hb1 = fma2(h21, t21, h21);   // i1
            ulonglong2 rA = *(const ulonglong2*)&rbs[c*8 + 0];
            ulonglong2 rB = *(const ulonglong2*)&rbs[c*8 + 2];
            ulonglong2 rC = *(const ulonglong2*)&rbs[c*8 + 4];
            ulonglong2 rD = *(const ulonglong2*)&rbs[c*8 + 6];
            accb0[0] = fma2(rA.x, hb0, accb0[0]); accb1[0] = fma2(rA.x, hb1, accb1[0]);
            accb0[1] = fma2(rA.y, hb0, accb0[1]); accb1[1] = fma2(rA.y, hb1, accb1[1]);
            accb0[2] = fma2(rB.x, hb0, accb0[2]); accb1[2] = fma2(rB.x, hb1, accb1[2]);
            accb0[3] = fma2(rB.y, hb0, accb0[3]); accb1[3] = fma2(rB.y, hb1, accb1[3]);
            accb0[4] = fma2(rC.x, hb0, accb0[4]); accb1[4] = fma2(rC.x, hb1, accb1[4]);
            accb0[5] = fma2(rC.y, hb0, accb0[5]); accb1[5] = fma2(rC.y, hb1, accb1[5]);
            accb0[6] = fma2(rD.x, hb0, accb0[6]); accb1[6] = fma2(rD.x, hb1, accb1[6]);
            accb0[7] = fma2(rD.y, hb0, accb0[7]); accb1[7] = fma2(rD.y, hb1, accb1[7]);
            s0 = fma2(pq1.x, k2v, s0);
            s1 = fma2(pq1.y, k2v, s1);
        }
        // fold scaled qk for the head whose c-range this segment is (ch warp-uniform)
        if (ch) { accb0[hs+4] = add2(accb0[hs+4], s0); accb1[hs+4] = add2(accb1[hs+4], s1); }
        else    { accb0[hs]   = add2(accb0[hs],   s0); accb1[hs]   = add2(accb1[hs],   s1); }
    }

    if (ch) {
        #pragma unroll
        for (int m = 0; m < 8; m++) {
            parts[m][jp]     = accb0[m];
            parts[m+8][jp]   = accb1[m];
        }
    }
    __syncthreads();
    if (!ch) {
        #pragma unroll
        for (int h = 0; h < NH; h++) {
            u64 v0 = add2(accb0[h], parts[h][jp]);
            u64 v1 = add2(accb1[h], parts[h+8][jp]);
            float rbb = rb2_b[h];
            float2 a0 = up2(v0), a1 = up2(v1);
            *(float2*)&g_scores[(i0*NH + h)*NTOK + 2*jp]     = make_float2(a0.x + rbb, a0.y + rbb);
            *(float2*)&g_scores[((i0+1)*NH + h)*NTOK + 2*jp] = make_float2(a1.x + rbb, a1.y + rbb);
        }
    }
}

// ---------------- attention ----------------
__global__ __launch_bounds__(256, 4) void attn_kernel(const float* __restrict__ x,
                                                      const float* __restrict__ rv1_b,
                                                      const float* __restrict__ rv2_b) {
    __shared__ float wT[NTOK*12];
    __shared__ float whid[NH*DIM];
    __shared__ float sinv[NH];
    int i = blockIdx.x, t = threadIdx.x;
    int wid = t >> 5, lane = t & 31;

    {
        const float* row = g_scores + (i*NH + wid)*NTOK;
        float m = -1e30f;
        for (int jj = lane; jj < NTOK; jj += 32) m = fmaxf(m, row[jj]);
        #pragma unroll
        for (int o = 16; o; o >>= 1) m = fmaxf(m, __shfl_xor_sync(0xffffffffu, m, o));
        float s = 0.f;
        for (int jj = lane; jj < NTOK; jj += 32) {
            float e = __expf(row[jj] - m);
            wT[jj*12 + wid] = e;
            s += e;
        }
        #pragma unroll
        for (int o = 16; o; o >>= 1) s += __shfl_xor_sync(0xffffffffu, s, o);
        if (lane == 0) sinv[wid] = __fdividef(1.0f, s);
    }
    __syncthreads();

    float pvih = 0.5f*rv1_b[t] - g_pvv[i*DIM + t].x;
    int hs = t >> 5;
    u64 accW[4] = {};
    float accC = 0.f;
    #pragma unroll 2
    for (int j = 0; j < NTOK; j++) {
        float2 pv = g_pvv[j*DIM + t];
        ulonglong2 wA = *(const ulonglong2*)&wT[j*12];
        ulonglong2 wB = *(const ulonglong2*)&wT[j*12 + 4];
        float hin = pvih + pv.x;
        float hv = fmaf(hin, ftanh(hin), hin);
        u64 hh = pk2(hv, hv);
        accW[0] = fma2(hh, wA.x, accW[0]); accW[1] = fma2(hh, wA.y, accW[1]);
        accW[2] = fma2(hh, wB.x, accW[2]); accW[3] = fma2(hh, wB.y, accW[3]);
        accC += wT[j*12 + hs] * pv.y;
    }
    #pragma unroll
    for (int hp = 0; hp < 4; hp++) {
        float2 v = up2(accW[hp]);
        whid[(2*hp)*DIM + t]   = v.x * sinv[2*hp];
        whid[(2*hp+1)*DIM + t] = v.y * sinv[2*hp+1];
    }
    accC *= sinv[hs];
    __syncthreads();

    float accP = 0.f;
    #pragma unroll 4
    for (int c = 0; c < DIM; c++)
        accP += whid[hs*DIM + c] * g_rv2T[c*DIM + t];

    g_resid[i*DIM + t] = x[i*DIM + t] + accC + accP + rv2_b[t];
}

// ---------------- FFN up (LN2 fused): 4 rows, 2 cols/thread, k-split 4 ----------------
__global__ __launch_bounds__(512) void ffn1_kernel(const float* __restrict__ ln2_w,
                                                   const float* __restrict__ ln2_b,
                                                   const float* __restrict__ b1,
                                                   const float* __restrict__ b2) {
    __shared__ float4 xs[DIM];
    __shared__ float2 red2[4][4];
    __shared__ u64 parta[128][3][4];
    __shared__ u64 partc[128][3][4];
    int t = threadIdx.x;
    int i0 = blockIdx.x * 4, chunk = blockIdx.y;
    block_ln4(g_resid, i0, ln2_w, ln2_b, xs, red2);

    int p = t & 127, kh = t >> 7;
    int o = chunk*256 + p*2;
    int ocl = (o <= HIDN-2) ? o : (HIDN-2);
    u64 a0=0, a1=0, a2=0, a3=0, c0=0, c1=0, c2=0, c3=0;
    int kbeg = kh * 64;
    #pragma unroll 4
    for (int kk = 0; kk < 64; kk++) {
        int k = kbeg + kk;
        float2 u2 = *(const float2*)&g_w1T[k*HIDN + ocl];
        float2 v2 = *(const float2*)&g_w2T[k*HIDN + ocl];
        ulonglong2 xv = *(const ulonglong2*)&xs[k];
        u64 u0 = pk2(u2.x,u2.x), u1 = pk2(u2.y,u2.y);
        u64 v0 = pk2(v2.x,v2.x), v1 = pk2(v2.y,v2.y);
        a0 = fma2(xv.x,u0,a0); a1 = fma2(xv.y,u0,a1);
        a2 = fma2(xv.x,u1,a2); a3 = fma2(xv.y,u1,a3);
        c0 = fma2(xv.x,v0,c0); c1 = fma2(xv.y,v0,c1);
        c2 = fma2(xv.x,v1,c2); c3 = fma2(xv.y,v1,c3);
    }
    if (kh) {
        parta[p][kh-1][0]=a0; parta[p][kh-1][1]=a1; parta[p][kh-1][2]=a2; parta[p][kh-1][3]=a3;
        partc[p][kh-1][0]=c0; partc[p][kh-1][1]=c1; partc[p][kh-1][2]=c2; partc[p][kh-1][3]=c3;
    }
    __syncthreads();
    if (kh == 0 && o < HIDN) {
        #pragma unroll
        for (int m = 0; m < 3; m++) {
            a0 = add2(a0, parta[p][m][0]); a1 = add2(a1, parta[p][m][1]);
            a2 = add2(a2, parta[p][m][2]); a3 = add2(a3, parta[p][m][3]);
            c0 = add2(c0, partc[p][m][0]); c1 = add2(c1, partc[p][m][1]);
            c2 = add2(c2, partc[p][m][2]); c3 = add2(c3, partc[p][m][3]);
        }
        float2 A0 = up2(a0), A1 = up2(a1), A2 = up2(a2), A3 = up2(a3);
        float2 C0 = up2(c0), C1 = up2(c1), C2 = up2(c2), C3 = up2(c3);
        float bb10 = b1[o], bb11 = b1[o+1], bb20 = b2[o], bb21 = b2[o+1];
        g_gate[(i0+0)*HIDN + o]   = fsilu(A0.x + bb10) * (C0.x + bb20);
        g_gate[(i0+1)*HIDN + o]   = fsilu(A0.y + bb10) * (C0.y + bb20);
        g_gate[(i0+2)*HIDN + o]   = fsilu(A1.x + bb10) * (C1.x + bb20);
        g_gate[(i0+3)*HIDN + o]   = fsilu(A1.y + bb10) * (C1.y + bb20);
        g_gate[(i0+0)*HIDN + o+1] = fsilu(A2.x + bb11) * (C2.x + bb21);
        g_gate[(i0+1)*HIDN + o+1] = fsilu(A2.y + bb11) * (C2.y + bb21);
        g_gate[(i0+2)*HIDN + o+1] = fsilu(A3.x + bb11) * (C3.x + bb21);
        g_gate[(i0+3)*HIDN + o+1] = fsilu(A3.y + bb11) * (C3.y + bb21);
    }
}

// ---------------- FFN down + residual: 2 rows, 2 cols/thread, o-split 4 ----------------
__global__ __launch_bounds__(512) void ffn2_kernel(const float* __restrict__ b3,
                                                   float* __restrict__ out) {
    __shared__ float2 gs[HIDN];
    __shared__ u64 part[128][3][2];
    int i0 = blockIdx.x * 2, t = threadIdx.x;
    int p = t & 127, oh = t >> 7;
    for (int idx = t; idx < HIDN; idx += 512)
        gs[idx] = make_float2(g_gate[i0*HIDN + idx], g_gate[(i0+1)*HIDN + idx]);
    __syncthreads();
    const int obeg[5] = {0, 171, 342, 512, 682};
    int os = obeg[oh], oe = obeg[oh+1];
    int d = p*2;
    u64 acc0 = 0, acc1 = 0;
    for (int o = os; o < oe; o++) {
        float2 w = *(const float2*)&g_w3T[o*DIM + d];
        u64 g2 = *(const u64*)&gs[o];
        acc0 = fma2(g2, pk2(w.x, w.x), acc0);
        acc1 = fma2(g2, pk2(w.y, w.y), acc1);
    }
    if (oh) { part[p][oh-1][0] = acc0; part[p][oh-1][1] = acc1; }
    __syncthreads();
    if (oh == 0) {
        #pragma unroll
        for (int m = 0; m < 3; m++) {
            acc0 = add2(acc0, part[p][m][0]);
            acc1 = add2(acc1, part[p][m][1]);
        }
        float2 A = up2(acc0), B = up2(acc1);
        float2 bb = *(const float2*)&b3[d];
        out[i0*DIM + d]       = g_resid[i0*DIM + d]       + A.x + bb.x;
        out[(i0+1)*DIM + d]   = g_resid[(i0+1)*DIM + d]   + A.y + bb.x;
        out[i0*DIM + d+1]     = g_resid[i0*DIM + d+1]     + B.x + bb.y;
        out[(i0+1)*DIM + d+1] = g_resid[(i0+1)*DIM + d+1] + B.y + bb.y;
    }
}

// ---------------- launch ----------------
extern "C" void kernel_launch(void* const* d_in, const int* in_sizes, int n_in,
                              void* d_out, int out_size) {
    const float* x      = (const float*)d_in[0];
    const float* coords = (const float*)d_in[1];
    const float* ln1_w  = (const float*)d_in[2];
    const float* ln1_b  = (const float*)d_in[3];
    const float* ln2_w  = (const float*)d_in[4];
    const float* ln2_b  = (const float*)d_in[5];
    const float* qkv_w  = (const float*)d_in[6];
    const float* qkv_b  = (const float*)d_in[7];
    const float* rb1_w  = (const float*)d_in[8];
    const float* rb1_b  = (const float*)d_in[9];
    const float* rb2_w  = (const float*)d_in[10];
    const float* rb2_b  = (const float*)d_in[11];
    const float* rv1_w  = (const float*)d_in[12];
    const float* rv1_b  = (const float*)d_in[13];
    const float* rv2_w  = (const float*)d_in[14];
    const float* rv2_b  = (const float*)d_in[15];
    const float* w1     = (const float*)d_in[16];
    const float* b1     = (const float*)d_in[17];
    const float* w2     = (const float*)d_in[18];
    const float* b2     = (const float*)d_in[19];
    const float* w3     = (const float*)d_in[20];
    const float* b3     = (const float*)d_in[21];
    float* out = (float*)d_out;

    prep_p<<<512, 256>>>(coords, rb1_w, rv1_w, rb2_w);
    tr_kernel<<<dim3(22, 24, 5), dim3(32, 8)>>>(qkv_w, rv2_w, w1, w2, w3);
    qkv_kernel<<<dim3(128, 3), 512>>>(x, ln1_w, ln1_b, qkv_b);
    scores_kernel<<<256, 512>>>(rb1_b, rb2_b);
    attn_kernel<<<NTOK, 256>>>(x, rv1_b, rv2_b);
    ffn1_kernel<<<dim3(128, 3), 512>>>(ln2_w, ln2_b, b1, b2);
    ffn2_kernel<<<256, 512>>>(b3, out);
}

// round 11
// speedup vs baseline: 1.1565x; 1.0582x over previous
#include <cuda_runtime.h>
#include <math.h>

#define NTOK 512
#define DIM 256
#define NH 8
#define HDIM 32
#define HIDN 682

typedef unsigned long long u64;

__device__ __forceinline__ u64 pk2(float lo, float hi) {
    u64 r; asm("mov.b64 %0, {%1,%2};" : "=l"(r) : "f"(lo), "f"(hi)); return r;
}
__device__ __forceinline__ float2 up2(u64 v) {
    float2 f; asm("mov.b64 {%0,%1}, %2;" : "=f"(f.x), "=f"(f.y) : "l"(v)); return f;
}
__device__ __forceinline__ u64 fma2(u64 a, u64 b, u64 c) {
    u64 d; asm("fma.rn.f32x2 %0, %1, %2, %3;" : "=l"(d) : "l"(a), "l"(b), "l"(c)); return d;
}
__device__ __forceinline__ u64 add2(u64 a, u64 b) {
    u64 d; asm("add.rn.f32x2 %0, %1, %2;" : "=l"(d) : "l"(a), "l"(b)); return d;
}
__device__ __forceinline__ float ftanh(float x) {
    float t; asm("tanh.approx.f32 %0, %1;" : "=f"(t) : "f"(x)); return t;
}
__device__ __forceinline__ float fsilu(float x) {
    float h = 0.5f * x;
    return fmaf(h, ftanh(h), h);
}

// ---------------- scratch ----------------
__device__ float g_q[NTOK*DIM];
__device__ float2 g_pb2[DIM*NTOK/2];   // [c][jp] = {-0.5*pb_{2jp}, -0.5*pb_{2jp+1}}
__device__ float2 g_k2[DIM*NTOK/2];    // [c][jp] = {k_{2jp}, k_{2jp+1}}
__device__ float4 g_pvv4[NTOK/2*DIM];  // [jp][c] = {-0.5pv_j0, -0.5pv_j1, v_j0, v_j1}
__device__ float2 g_rv2p[DIM/2*DIM];   // [cp][o] = {rv2T[2cp][o], rv2T[2cp+1][o]}
__device__ u64   g_rb2d[DIM*NH];       // [c][h] duplicated pairs
__device__ float g_qkvT[DIM*3*DIM];    // [k][o]
__device__ float g_w1T[DIM*HIDN];      // [k][o]
__device__ float g_w2T[DIM*HIDN];
__device__ float g_w3T[HIDN*DIM];      // [o][d]
__device__ float g_scores[NTOK*NH*NTOK]; // [i][h][j]
__device__ float g_resid[NTOK*DIM];
__device__ float g_gate[NTOK*HIDN];

// ---------------- prep: P matrices (prescaled) + rb2 dup + rv2 pair ----------------
__global__ void prep_p(const float* __restrict__ coords,
                       const float* __restrict__ rb1_w,
                       const float* __restrict__ rv1_w,
                       const float* __restrict__ rb2_w,
                       const float* __restrict__ rv2_w) {
    int idx = blockIdx.x * 256 + threadIdx.x;   // 512 blocks -> 131072
    {
        int c = idx >> 9, n = idx & 511;        // [c][n]
        float x0 = coords[n*3+0], x1 = coords[n*3+1], x2 = coords[n*3+2];
        float pb = x0*rb1_w[c*3+0] + x1*rb1_w[c*3+1] + x2*rb1_w[c*3+2];
        ((float*)g_pb2)[idx] = -0.5f * pb;
    }
    if (idx < 65536) {                           // pvv4 .x/.y
        int jp = idx >> 8, c = idx & 255;
        int j0 = 2*jp, j1 = j0 + 1;
        float w0 = rv1_w[c*3+0], w1 = rv1_w[c*3+1], w2 = rv1_w[c*3+2];
        float pv0 = coords[j0*3+0]*w0 + coords[j0*3+1]*w1 + coords[j0*3+2]*w2;
        float pv1 = coords[j1*3+0]*w0 + coords[j1*3+1]*w1 + coords[j1*3+2]*w2;
        *(float2*)&g_pvv4[idx] = make_float2(-0.5f*pv0, -0.5f*pv1);
    }
    if (idx < 32768) {                           // rv2 c-pair: rv2T[c][o] = rv2_w[o*DIM+c]
        int o = idx >> 7, cp = idx & 127;
        float2 rv = *(const float2*)&rv2_w[o*DIM + 2*cp];
        g_rv2p[cp*DIM + o] = rv;
    }
    if (idx < NH*DIM) {
        int h = idx / DIM, c = idx % DIM;
        float r = rb2_w[idx];
        g_rb2d[c*NH + h] = pk2(r, r);
    }
}

// ---------------- tiled transposes ----------------
__global__ void tr_kernel(const float* __restrict__ qkv_w,
                          const float* __restrict__ w1,
                          const float* __restrict__ w2,
                          const float* __restrict__ w3) {
    __shared__ float tile[32][33];
    const float* src; float* dst; int R, C;
    switch (blockIdx.z) {
        case 0: src = qkv_w; dst = g_qkvT; R = 768; C = 256; break;
        case 1: src = w1;    dst = g_w1T;  R = HIDN; C = 256; break;
        case 2: src = w2;    dst = g_w2T;  R = HIDN; C = 256; break;
        default: src = w3;   dst = g_w3T;  R = 256; C = HIDN; break;
    }
    int bx = blockIdx.x * 32, by = blockIdx.y * 32;
    if (bx >= C || by >= R) return;
    int tx = threadIdx.x, ty = threadIdx.y;
    #pragma unroll
    for (int dy = ty; dy < 32; dy += 8) {
        int r = by + dy, cc = bx + tx;
        if (r < R && cc < C) tile[dy][tx] = src[r*C + cc];
    }
    __syncthreads();
    #pragma unroll
    for (int dy = ty; dy < 32; dy += 8) {
        int r = bx + dy, cc = by + tx;   // dst is [C][R]
        if (r < C && cc < R) dst[r*R + cc] = tile[tx][dy];
    }
}

// ---- in-block LayerNorm of 4 rows into xs[c] (float4 over rows) ----
__device__ __forceinline__ void block_ln4(const float* __restrict__ src, int i0,
                                          const float* __restrict__ lnw,
                                          const float* __restrict__ lnb,
                                          float4* xs, float2 (*red2)[4]) {
    int t = threadIdx.x;
    int lane = t & 31, r = t >> 7, wir = (t >> 5) & 3;
    int cc = (t & 127) * 2;
    float2 xv = *(const float2*)&src[(i0+r)*DIM + cc];
    float s1 = xv.x + xv.y;
    float s2 = fmaf(xv.x, xv.x, xv.y*xv.y);
    #pragma unroll
    for (int o = 16; o; o >>= 1) {
        s1 += __shfl_xor_sync(0xffffffffu, s1, o);
        s2 += __shfl_xor_sync(0xffffffffu, s2, o);
    }
    if (lane == 0) red2[r][wir] = make_float2(s1, s2);
    __syncthreads();
    float S1 = red2[r][0].x + red2[r][1].x + red2[r][2].x + red2[r][3].x;
    float S2 = red2[r][0].y + red2[r][1].y + red2[r][2].y + red2[r][3].y;
    float mean = S1 * (1.0f/256.0f);
    float var  = S2 * (1.0f/256.0f) - mean*mean;
    float inv  = rsqrtf(var + 1e-5f);
    float2 wv = *(const float2*)&lnw[cc];
    float2 bv = *(const float2*)&lnb[cc];
    ((float*)&xs[cc])[r]   = (xv.x - mean)*inv*wv.x + bv.x;
    ((float*)&xs[cc+1])[r] = (xv.y - mean)*inv*wv.y + bv.y;
    __syncthreads();
}

// ---------------- QKV (LN1 fused): 4 rows, 256-col chunk, 2 cols/thread, k-split 4 ----------------
__global__ __launch_bounds__(512) void qkv_kernel(const float* __restrict__ x,
                                                  const float* __restrict__ ln1_w,
                                                  const float* __restrict__ ln1_b,
                                                  const float* __restrict__ qkv_b) {
    __shared__ float4 xs[DIM];
    __shared__ float2 red2[4][4];
    __shared__ u64 part[128][3][4];
    int t = threadIdx.x;
    int i0 = blockIdx.x * 4, chunk = blockIdx.y;
    block_ln4(x, i0, ln1_w, ln1_b, xs, red2);

    int p = t & 127, kh = t >> 7;
    int ob = chunk*256 + p*2;
    u64 a0 = 0, a1 = 0, b0 = 0, b1 = 0;
    int kbeg = kh * 64;
    #pragma unroll 4
    for (int kk = 0; kk < 64; kk++) {
        int k = kbeg + kk;
        float2 w2 = *(const float2*)&g_qkvT[k*768 + ob];
        ulonglong2 xv = *(const ulonglong2*)&xs[k];
        u64 w0 = pk2(w2.x, w2.x), w1 = pk2(w2.y, w2.y);
        a0 = fma2(xv.x, w0, a0); a1 = fma2(xv.y, w0, a1);
        b0 = fma2(xv.x, w1, b0); b1 = fma2(xv.y, w1, b1);
    }
    if (kh) { part[p][kh-1][0]=a0; part[p][kh-1][1]=a1; part[p][kh-1][2]=b0; part[p][kh-1][3]=b1; }
    __syncthreads();
    if (kh == 0) {
        #pragma unroll
        for (int m = 0; m < 3; m++) {
            a0 = add2(a0, part[p][m][0]); a1 = add2(a1, part[p][m][1]);
            b0 = add2(b0, part[p][m][2]); b1 = add2(b1, part[p][m][3]);
        }
        float2 bb = *(const float2*)&qkv_b[ob];
        float2 A = up2(a0), B = up2(a1), C = up2(b0), D = up2(b1);
        float r0[4] = { A.x+bb.x, A.y+bb.x, B.x+bb.x, B.y+bb.x };   // col ob, rows 0..3
        float r1[4] = { C.x+bb.y, C.y+bb.y, D.x+bb.y, D.y+bb.y };   // col ob+1
        if (chunk == 0) {
            #pragma unroll
            for (int rr = 0; rr < 4; rr++) {
                g_q[(i0+rr)*DIM + ob]   = r0[rr];
                g_q[(i0+rr)*DIM + ob+1] = r1[rr];
            }
        } else if (chunk == 1) {
            int c0 = ob - 256, jp = i0 >> 1;
            g_k2[c0*256 + jp]       = make_float2(r0[0], r0[1]);
            g_k2[c0*256 + jp + 1]   = make_float2(r0[2], r0[3]);
            g_k2[(c0+1)*256 + jp]   = make_float2(r1[0], r1[1]);
            g_k2[(c0+1)*256 + jp+1] = make_float2(r1[2], r1[3]);
        } else {
            int c0 = ob - 512, jp = i0 >> 1;
            float* base = (float*)g_pvv4;   // float4 [jp][c], v at .z/.w
            *(float2*)&base[((jp  )*256 + c0  )*4 + 2] = make_float2(r0[0], r0[1]);
            *(float2*)&base[((jp+1)*256 + c0  )*4 + 2] = make_float2(r0[2], r0[3]);
            *(float2*)&base[((jp  )*256 + c0+1)*4 + 2] = make_float2(r1[0], r1[1]);
            *(float2*)&base[((jp+1)*256 + c0+1)*4 + 2] = make_float2(r1[2], r1[3]);
        }
    }
}

// ---------------- scores: 2 i x 512 j per block, j-pair x c-half per thread ----------------
__global__ __launch_bounds__(512, 2) void scores_kernel(const float* __restrict__ rb1_b,
                                                        const float* __restrict__ rb2_b) {
    __shared__ ulonglong2 phq[DIM][2];  // [c] = {ph0_dup, ph1_dup}, {q0s_dup, q1s_dup}
    __shared__ u64 rbs[DIM*NH];         // 16KB duplicated rb2
    __shared__ u64 parts[16][256];      // [m][jp] partials from upper c-half
    int i0 = blockIdx.x * 2;
    int t = threadIdx.x;
    int jp = t & 255, ch = t >> 8;      // ch: c-half (warp-uniform)
    const float sc = 0.17677669529663687f;

    if (t < 256) {
        float bh = 0.5f * rb1_b[t];
        float2 pbi = g_pb2[t*256 + (i0 >> 1)];  // {-½pb_i0, -½pb_i1}
        float p0 = bh - pbi.x, p1 = bh - pbi.y;
        float q0 = g_q[i0*DIM + t] * sc, q1 = g_q[(i0+1)*DIM + t] * sc;
        phq[t][0] = make_ulonglong2(pk2(p0, p0), pk2(p1, p1));
        phq[t][1] = make_ulonglong2(pk2(q0, q0), pk2(q1, q1));
    }
    #pragma unroll
    for (int m = 0; m < 4; m++) rbs[m*512 + t] = g_rb2d[m*512 + t];
    __syncthreads();

    const u64* pbp = (const u64*)g_pb2 + jp;
    const u64* kp  = (const u64*)g_k2 + jp;
    int cbase = ch * 128;

    u64 accb0[8] = {}, accb1[8] = {};
    #pragma unroll
    for (int hs = 0; hs < 4; hs++) {
        u64 s0 = 0, s1 = 0;
        #pragma unroll 4
        for (int c32 = 0; c32 < 32; c32++) {
            int c = cbase + hs*32 + c32;
            u64 pb2v = pbp[c*256];
            u64 k2v  = kp[c*256];
            ulonglong2 pq0 = phq[c][0];
            ulonglong2 pq1 = phq[c][1];
            u64 h20 = add2(pq0.x, pb2v);
            u64 h21 = add2(pq0.y, pb2v);
            float2 f0 = up2(h20), f1 = up2(h21);
            u64 t20 = pk2(ftanh(f0.x), ftanh(f0.y));
            u64 t21 = pk2(ftanh(f1.x), ftanh(f1.y));
            u64 hb0 = fma2(h20, t20, h20);
            u64 hb1 = fma2(h21, t21, h21);
            ulonglong2 rA = *(const ulonglong2*)&rbs[c*8 + 0];
            ulonglong2 rB = *(const ulonglong2*)&rbs[c*8 + 2];
            ulonglong2 rC = *(const ulonglong2*)&rbs[c*8 + 4];
            ulonglong2 rD = *(const ulonglong2*)&rbs[c*8 + 6];
            accb0[0] = fma2(rA.x, hb0, accb0[0]); accb1[0] = fma2(rA.x, hb1, accb1[0]);
            accb0[1] = fma2(rA.y, hb0, accb0[1]); accb1[1] = fma2(rA.y, hb1, accb1[1]);
            accb0[2] = fma2(rB.x, hb0, accb0[2]); accb1[2] = fma2(rB.x, hb1, accb1[2]);
            accb0[3] = fma2(rB.y, hb0, accb0[3]); accb1[3] = fma2(rB.y, hb1, accb1[3]);
            accb0[4] = fma2(rC.x, hb0, accb0[4]); accb1[4] = fma2(rC.x, hb1, accb1[4]);
            accb0[5] = fma2(rC.y, hb0, accb0[5]); accb1[5] = fma2(rC.y, hb1, accb1[5]);
            accb0[6] = fma2(rD.x, hb0, accb0[6]); accb1[6] = fma2(rD.x, hb1, accb1[6]);
            accb0[7] = fma2(rD.y, hb0, accb0[7]); accb1[7] = fma2(rD.y, hb1, accb1[7]);
            s0 = fma2(pq1.x, k2v, s0);
            s1 = fma2(pq1.y, k2v, s1);
        }
        if (ch) { accb0[hs+4] = add2(accb0[hs+4], s0); accb1[hs+4] = add2(accb1[hs+4], s1); }
        else    { accb0[hs]   = add2(accb0[hs],   s0); accb1[hs]   = add2(accb1[hs],   s1); }
    }

    if (ch) {
        #pragma unroll
        for (int m = 0; m < 8; m++) {
            parts[m][jp]   = accb0[m];
            parts[m+8][jp] = accb1[m];
        }
    }
    __syncthreads();
    if (!ch) {
        #pragma unroll
        for (int h = 0; h < NH; h++) {
            u64 v0 = add2(accb0[h], parts[h][jp]);
            u64 v1 = add2(accb1[h], parts[h+8][jp]);
            float rbb = rb2_b[h];
            float2 a0 = up2(v0), a1 = up2(v1);
            *(float2*)&g_scores[(i0*NH + h)*NTOK + 2*jp]     = make_float2(a0.x + rbb, a0.y + rbb);
            *(float2*)&g_scores[((i0+1)*NH + h)*NTOK + 2*jp] = make_float2(a1.x + rbb, a1.y + rbb);
        }
    }
}

// ---------------- attention: j-pair packed ----------------
__global__ __launch_bounds__(256, 5) void attn_kernel(const float* __restrict__ x,
                                                      const float* __restrict__ rv1_b,
                                                      const float* __restrict__ rv2_b) {
    __shared__ ulonglong2 wT2v[NTOK/2*5];   // [jp][h] j-pair weights, stride 10 u64 (20KB)
    __shared__ float whid[NH*DIM];
    __shared__ float sinv[NH];
    u64* wT2 = (u64*)wT2v;
    int i = blockIdx.x, t = threadIdx.x;
    int wid = t >> 5, lane = t & 31;

    { // unnormalized softmax for head wid; store as j-pairs
        const float* row = g_scores + (i*NH + wid)*NTOK;
        float m = -1e30f;
        for (int jj = lane; jj < NTOK; jj += 32) m = fmaxf(m, row[jj]);
        #pragma unroll
        for (int o = 16; o; o >>= 1) m = fmaxf(m, __shfl_xor_sync(0xffffffffu, m, o));
        float s = 0.f;
        for (int jj = lane; jj < NTOK; jj += 32) {
            float e = __expf(row[jj] - m);
            ((float*)wT2)[((jj >> 1)*10 + wid)*2 + (jj & 1)] = e;
            s += e;
        }
        #pragma unroll
        for (int o = 16; o; o >>= 1) s += __shfl_xor_sync(0xffffffffu, s, o);
        if (lane == 0) sinv[wid] = __fdividef(1.0f, s);
    }
    __syncthreads();

    u64 pvih2;
    {
        float2 p2 = *(const float2*)&g_pvv4[(i >> 1)*DIM + t];
        float pvih = 0.5f*rv1_b[t] - ((i & 1) ? p2.y : p2.x);
        pvih2 = pk2(pvih, pvih);
    }
    int hs = t >> 5;
    u64 accW[8] = {};
    u64 accC = 0;
    for (int jjp = 0; jjp < NTOK/2; jjp++) {
        float4 pv4 = g_pvv4[jjp*DIM + t];         // {-½pv_j0, -½pv_j1, v_j0, v_j1}
        u64 pv2 = pk2(pv4.x, pv4.y);
        u64 h2 = add2(pvih2, pv2);
        float2 f = up2(h2);
        u64 t2 = pk2(ftanh(f.x), ftanh(f.y));
        u64 hb2 = fma2(h2, t2, h2);               // {hv_j0, hv_j1}
        const u64* wrow = wT2 + jjp*10;
        ulonglong2 wA = *(const ulonglong2*)&wrow[0];
        ulonglong2 wB = *(const ulonglong2*)&wrow[2];
        ulonglong2 wC = *(const ulonglong2*)&wrow[4];
        ulonglong2 wD = *(const ulonglong2*)&wrow[6];
        accW[0] = fma2(hb2, wA.x, accW[0]); accW[1] = fma2(hb2, wA.y, accW[1]);
        accW[2] = fma2(hb2, wB.x, accW[2]); accW[3] = fma2(hb2, wB.y, accW[3]);
        accW[4] = fma2(hb2, wC.x, accW[4]); accW[5] = fma2(hb2, wC.y, accW[5]);
        accW[6] = fma2(hb2, wD.x, accW[6]); accW[7] = fma2(hb2, wD.y, accW[7]);
        u64 v2 = pk2(pv4.z, pv4.w);
        accC = fma2(wrow[hs], v2, accC);          // warp-uniform LDS broadcast
    }
    #pragma unroll
    for (int h = 0; h < NH; h++) {
        float2 v = up2(accW[h]);
        whid[h*DIM + t] = (v.x + v.y) * sinv[h];
    }
    float accCf;
    { float2 fc = up2(accC); accCf = (fc.x + fc.y) * sinv[hs]; }
    __syncthreads();

    u64 accP2 = 0;
    #pragma unroll 4
    for (int cp = 0; cp < DIM/2; cp++) {
        u64 wh = *(const u64*)&whid[hs*DIM + 2*cp];   // broadcast pair
        float2 rv = g_rv2p[cp*DIM + t];
        accP2 = fma2(wh, pk2(rv.x, rv.y), accP2);
    }
    float2 fp = up2(accP2);
    g_resid[i*DIM + t] = x[i*DIM + t] + accCf + fp.x + fp.y + rv2_b[t];
}

// ---------------- FFN up (LN2 fused): 4 rows, 2 cols/thread, k-split 4 ----------------
__global__ __launch_bounds__(512) void ffn1_kernel(const float* __restrict__ ln2_w,
                                                   const float* __restrict__ ln2_b,
                                                   const float* __restrict__ b1,
                                                   const float* __restrict__ b2) {
    __shared__ float4 xs[DIM];
    __shared__ float2 red2[4][4];
    __shared__ u64 parta[128][3][4];
    __shared__ u64 partc[128][3][4];
    int t = threadIdx.x;
    int i0 = blockIdx.x * 4, chunk = blockIdx.y;
    block_ln4(g_resid, i0, ln2_w, ln2_b, xs, red2);

    int p = t & 127, kh = t >> 7;
    int o = chunk*256 + p*2;
    int ocl = (o <= HIDN-2) ? o : (HIDN-2);
    u64 a0=0, a1=0, a2=0, a3=0, c0=0, c1=0, c2=0, c3=0;
    int kbeg = kh * 64;
    #pragma unroll 4
    for (int kk = 0; kk < 64; kk++) {
        int k = kbeg + kk;
        float2 u2 = *(const float2*)&g_w1T[k*HIDN + ocl];
        float2 v2 = *(const float2*)&g_w2T[k*HIDN + ocl];
        ulonglong2 xv = *(const ulonglong2*)&xs[k];
        u64 u0 = pk2(u2.x,u2.x), u1 = pk2(u2.y,u2.y);
        u64 v0 = pk2(v2.x,v2.x), v1 = pk2(v2.y,v2.y);
        a0 = fma2(xv.x,u0,a0); a1 = fma2(xv.y,u0,a1);
        a2 = fma2(xv.x,u1,a2); a3 = fma2(xv.y,u1,a3);
        c0 = fma2(xv.x,v0,c0); c1 = fma2(xv.y,v0,c1);
        c2 = fma2(xv.x,v1,c2); c3 = fma2(xv.y,v1,c3);
    }
    if (kh) {
        parta[p][kh-1][0]=a0; parta[p][kh-1][1]=a1; parta[p][kh-1][2]=a2; parta[p][kh-1][3]=a3;
        partc[p][kh-1][0]=c0; partc[p][kh-1][1]=c1; partc[p][kh-1][2]=c2; partc[p][kh-1][3]=c3;
    }
    __syncthreads();
    if (kh == 0 && o < HIDN) {
        #pragma unroll
        for (int m = 0; m < 3; m++) {
            a0 = add2(a0, parta[p][m][0]); a1 = add2(a1, parta[p][m][1]);
            a2 = add2(a2, parta[p][m][2]); a3 = add2(a3, parta[p][m][3]);
            c0 = add2(c0, partc[p][m][0]); c1 = add2(c1, partc[p][m][1]);
            c2 = add2(c2, partc[p][m][2]); c3 = add2(c3, partc[p][m][3]);
        }
        float2 A0 = up2(a0), A1 = up2(a1), A2 = up2(a2), A3 = up2(a3);
        float2 C0 = up2(c0), C1 = up2(c1), C2 = up2(c2), C3 = up2(c3);
        float bb10 = b1[o], bb11 = b1[o+1], bb20 = b2[o], bb21 = b2[o+1];
        g_gate[(i0+0)*HIDN + o]   = fsilu(A0.x + bb10) * (C0.x + bb20);
        g_gate[(i0+1)*HIDN + o]   = fsilu(A0.y + bb10) * (C0.y + bb20);
        g_gate[(i0+2)*HIDN + o]   = fsilu(A1.x + bb10) * (C1.x + bb20);
        g_gate[(i0+3)*HIDN + o]   = fsilu(A1.y + bb10) * (C1.y + bb20);
        g_gate[(i0+0)*HIDN + o+1] = fsilu(A2.x + bb11) * (C2.x + bb21);
        g_gate[(i0+1)*HIDN + o+1] = fsilu(A2.y + bb11) * (C2.y + bb21);
        g_gate[(i0+2)*HIDN + o+1] = fsilu(A3.x + bb11) * (C3.x + bb21);
        g_gate[(i0+3)*HIDN + o+1] = fsilu(A3.y + bb11) * (C3.y + bb21);
    }
}

// ---------------- FFN down + residual: 2 rows, 2 cols/thread, o-split 4 ----------------
__global__ __launch_bounds__(512) void ffn2_kernel(const float* __restrict__ b3,
                                                   float* __restrict__ out) {
    __shared__ float2 gs[HIDN];
    __shared__ u64 part[128][3][2];
    int i0 = blockIdx.x * 2, t = threadIdx.x;
    int p = t & 127, oh = t >> 7;
    for (int idx = t; idx < HIDN; idx += 512)
        gs[idx] = make_float2(g_gate[i0*HIDN + idx], g_gate[(i0+1)*HIDN + idx]);
    __syncthreads();
    const int obeg[5] = {0, 171, 342, 512, 682};
    int os = obeg[oh], oe = obeg[oh+1];
    int d = p*2;
    u64 acc0 = 0, acc1 = 0;
    for (int o = os; o < oe; o++) {
        float2 w = *(const float2*)&g_w3T[o*DIM + d];
        u64 g2 = *(const u64*)&gs[o];
        acc0 = fma2(g2, pk2(w.x, w.x), acc0);
        acc1 = fma2(g2, pk2(w.y, w.y), acc1);
    }
    if (oh) { part[p][oh-1][0] = acc0; part[p][oh-1][1] = acc1; }
    __syncthreads();
    if (oh == 0) {
        #pragma unroll
        for (int m = 0; m < 3; m++) {
            acc0 = add2(acc0, part[p][m][0]);
            acc1 = add2(acc1, part[p][m][1]);
        }
        float2 A = up2(acc0), B = up2(acc1);
        float2 bb = *(const float2*)&b3[d];
        out[i0*DIM + d]       = g_resid[i0*DIM + d]       + A.x + bb.x;
        out[(i0+1)*DIM + d]   = g_resid[(i0+1)*DIM + d]   + A.y + bb.x;
        out[i0*DIM + d+1]     = g_resid[i0*DIM + d+1]     + B.x + bb.y;
        out[(i0+1)*DIM + d+1] = g_resid[(i0+1)*DIM + d+1] + B.y + bb.y;
    }
}

// ---------------- launch ----------------
extern "C" void kernel_launch(void* const* d_in, const int* in_sizes, int n_in,
                              void* d_out, int out_size) {
    const float* x      = (const float*)d_in[0];
    const float* coords = (const float*)d_in[1];
    const float* ln1_w  = (const float*)d_in[2];
    const float* ln1_b  = (const float*)d_in[3];
    const float* ln2_w  = (const float*)d_in[4];
    const float* ln2_b  = (const float*)d_in[5];
    const float* qkv_w  = (const float*)d_in[6];
    const float* qkv_b  = (const float*)d_in[7];
    const float* rb1_w  = (const float*)d_in[8];
    const float* rb1_b  = (const float*)d_in[9];
    const float* rb2_w  = (const float*)d_in[10];
    const float* rb2_b  = (const float*)d_in[11];
    const float* rv1_w  = (const float*)d_in[12];
    const float* rv1_b  = (const float*)d_in[13];
    const float* rv2_w  = (const float*)d_in[14];
    const float* rv2_b  = (const float*)d_in[15];
    const float* w1     = (const float*)d_in[16];
    const float* b1     = (const float*)d_in[17];
    const float* w2     = (const float*)d_in[18];
    const float* b2     = (const float*)d_in[19];
    const float* w3     = (const float*)d_in[20];
    const float* b3     = (const float*)d_in[21];
    float* out = (float*)d_out;

    prep_p<<<512, 256>>>(coords, rb1_w, rv1_w, rb2_w, rv2_w);
    tr_kernel<<<dim3(22, 24, 4), dim3(32, 8)>>>(qkv_w, w1, w2, w3);
    qkv_kernel<<<dim3(128, 3), 512>>>(x, ln1_w, ln1_b, qkv_b);
    scores_kernel<<<256, 512>>>(rb1_b, rb2_b);
    attn_kernel<<<NTOK, 256>>>(x, rv1_b, rv2_b);
    ffn1_kernel<<<dim3(128, 3), 512>>>(ln2_w, ln2_b, b1, b2);
    ffn2_kernel<<<256, 512>>>(b3, out);
}

// round 12
// speedup vs baseline: 1.1624x; 1.0051x over previous
#include <cuda_runtime.h>
#include <math.h>

#define NTOK 512
#define DIM 256
#define NH 8
#define HDIM 32
#define HIDN 682

typedef unsigned long long u64;

__device__ __forceinline__ u64 pk2(float lo, float hi) {
    u64 r; asm("mov.b64 %0, {%1,%2};" : "=l"(r) : "f"(lo), "f"(hi)); return r;
}
__device__ __forceinline__ float2 up2(u64 v) {
    float2 f; asm("mov.b64 {%0,%1}, %2;" : "=f"(f.x), "=f"(f.y) : "l"(v)); return f;
}
__device__ __forceinline__ u64 fma2(u64 a, u64 b, u64 c) {
    u64 d; asm("fma.rn.f32x2 %0, %1, %2, %3;" : "=l"(d) : "l"(a), "l"(b), "l"(c)); return d;
}
__device__ __forceinline__ u64 add2(u64 a, u64 b) {
    u64 d; asm("add.rn.f32x2 %0, %1, %2;" : "=l"(d) : "l"(a), "l"(b)); return d;
}
__device__ __forceinline__ float ftanh(float x) {
    float t; asm("tanh.approx.f32 %0, %1;" : "=f"(t) : "f"(x)); return t;
}
__device__ __forceinline__ float fsilu(float x) {
    float h = 0.5f * x;
    return fmaf(h, ftanh(h), h);
}

// ---------------- scratch ----------------
__device__ float g_q[NTOK*DIM];
__device__ float2 g_pb2[DIM*NTOK/2];   // [c][jp] = {-0.5*pb_{2jp}, -0.5*pb_{2jp+1}}
__device__ float2 g_k2[DIM*NTOK/2];    // [c][jp] = {k_{2jp}, k_{2jp+1}}
__device__ float4 g_pvv4[NTOK/2*DIM];  // [jp][c] = {-0.5pv_j0, -0.5pv_j1, v_j0, v_j1}
__device__ float2 g_rv2p[DIM/2*DIM];   // [cp][o] = {rv2T[2cp][o], rv2T[2cp+1][o]}
__device__ u64   g_rb2d[DIM*NH];       // [c][h] duplicated pairs (staging for constant)
__constant__ u64 c_rb2d[DIM*NH];       // 16KB: read via constant port (LDCU), no L1 traffic
__device__ float g_qkvT[DIM*3*DIM];    // [k][o]
__device__ float g_w1T[DIM*HIDN];      // [k][o]
__device__ float g_w2T[DIM*HIDN];
__device__ float g_w3T[HIDN*DIM];      // [o][d]
__device__ float g_scores[NTOK*NH*NTOK]; // [i][h][j]
__device__ float g_resid[NTOK*DIM];
__device__ float g_gate[NTOK*HIDN];

// ---------------- prep: P matrices (prescaled) + rb2 dup + rv2 pair ----------------
__global__ void prep_p(const float* __restrict__ coords,
                       const float* __restrict__ rb1_w,
                       const float* __restrict__ rv1_w,
                       const float* __restrict__ rb2_w,
                       const float* __restrict__ rv2_w) {
    int idx = blockIdx.x * 256 + threadIdx.x;   // 512 blocks -> 131072
    {
        int c = idx >> 9, n = idx & 511;        // [c][n]
        float x0 = coords[n*3+0], x1 = coords[n*3+1], x2 = coords[n*3+2];
        float pb = x0*rb1_w[c*3+0] + x1*rb1_w[c*3+1] + x2*rb1_w[c*3+2];
        ((float*)g_pb2)[idx] = -0.5f * pb;
    }
    if (idx < 65536) {                           // pvv4 .x/.y
        int jp = idx >> 8, c = idx & 255;
        int j0 = 2*jp, j1 = j0 + 1;
        float w0 = rv1_w[c*3+0], w1 = rv1_w[c*3+1], w2 = rv1_w[c*3+2];
        float pv0 = coords[j0*3+0]*w0 + coords[j0*3+1]*w1 + coords[j0*3+2]*w2;
        float pv1 = coords[j1*3+0]*w0 + coords[j1*3+1]*w1 + coords[j1*3+2]*w2;
        *(float2*)&g_pvv4[idx] = make_float2(-0.5f*pv0, -0.5f*pv1);
    }
    if (idx < 32768) {                           // rv2 c-pair: rv2T[c][o] = rv2_w[o*DIM+c]
        int o = idx >> 7, cp = idx & 127;
        float2 rv = *(const float2*)&rv2_w[o*DIM + 2*cp];
        g_rv2p[cp*DIM + o] = rv;
    }
    if (idx < NH*DIM) {
        int h = idx / DIM, c = idx % DIM;
        float r = rb2_w[idx];
        g_rb2d[c*NH + h] = pk2(r, r);
    }
}

// ---------------- tiled transposes ----------------
__global__ void tr_kernel(const float* __restrict__ qkv_w,
                          const float* __restrict__ w1,
                          const float* __restrict__ w2,
                          const float* __restrict__ w3) {
    __shared__ float tile[32][33];
    const float* src; float* dst; int R, C;
    switch (blockIdx.z) {
        case 0: src = qkv_w; dst = g_qkvT; R = 768; C = 256; break;
        case 1: src = w1;    dst = g_w1T;  R = HIDN; C = 256; break;
        case 2: src = w2;    dst = g_w2T;  R = HIDN; C = 256; break;
        default: src = w3;   dst = g_w3T;  R = 256; C = HIDN; break;
    }
    int bx = blockIdx.x * 32, by = blockIdx.y * 32;
    if (bx >= C || by >= R) return;
    int tx = threadIdx.x, ty = threadIdx.y;
    #pragma unroll
    for (int dy = ty; dy < 32; dy += 8) {
        int r = by + dy, cc = bx + tx;
        if (r < R && cc < C) tile[dy][tx] = src[r*C + cc];
    }
    __syncthreads();
    #pragma unroll
    for (int dy = ty; dy < 32; dy += 8) {
        int r = bx + dy, cc = by + tx;   // dst is [C][R]
        if (r < C && cc < R) dst[r*R + cc] = tile[tx][dy];
    }
}

// ---- in-block LayerNorm of 4 rows into xs[c] (float4 over rows) ----
__device__ __forceinline__ void block_ln4(const float* __restrict__ src, int i0,
                                          const float* __restrict__ lnw,
                                          const float* __restrict__ lnb,
                                          float4* xs, float2 (*red2)[4]) {
    int t = threadIdx.x;
    int lane = t & 31, r = t >> 7, wir = (t >> 5) & 3;
    int cc = (t & 127) * 2;
    float2 xv = *(const float2*)&src[(i0+r)*DIM + cc];
    float s1 = xv.x + xv.y;
    float s2 = fmaf(xv.x, xv.x, xv.y*xv.y);
    #pragma unroll
    for (int o = 16; o; o >>= 1) {
        s1 += __shfl_xor_sync(0xffffffffu, s1, o);
        s2 += __shfl_xor_sync(0xffffffffu, s2, o);
    }
    if (lane == 0) red2[r][wir] = make_float2(s1, s2);
    __syncthreads();
    float S1 = red2[r][0].x + red2[r][1].x + red2[r][2].x + red2[r][3].x;
    float S2 = red2[r][0].y + red2[r][1].y + red2[r][2].y + red2[r][3].y;
    float mean = S1 * (1.0f/256.0f);
    float var  = S2 * (1.0f/256.0f) - mean*mean;
    float inv  = rsqrtf(var + 1e-5f);
    float2 wv = *(const float2*)&lnw[cc];
    float2 bv = *(const float2*)&lnb[cc];
    ((float*)&xs[cc])[r]   = (xv.x - mean)*inv*wv.x + bv.x;
    ((float*)&xs[cc+1])[r] = (xv.y - mean)*inv*wv.y + bv.y;
    __syncthreads();
}

// ---------------- QKV (LN1 fused): 4 rows, 256-col chunk, 2 cols/thread, k-split 4 ----------------
__global__ __launch_bounds__(512) void qkv_kernel(const float* __restrict__ x,
                                                  const float* __restrict__ ln1_w,
                                                  const float* __restrict__ ln1_b,
                                                  const float* __restrict__ qkv_b) {
    __shared__ float4 xs[DIM];
    __shared__ float2 red2[4][4];
    __shared__ u64 part[128][3][4];
    int t = threadIdx.x;
    int i0 = blockIdx.x * 4, chunk = blockIdx.y;
    block_ln4(x, i0, ln1_w, ln1_b, xs, red2);

    int p = t & 127, kh = t >> 7;
    int ob = chunk*256 + p*2;
    u64 a0 = 0, a1 = 0, b0 = 0, b1 = 0;
    int kbeg = kh * 64;
    #pragma unroll 4
    for (int kk = 0; kk < 64; kk++) {
        int k = kbeg + kk;
        float2 w2 = *(const float2*)&g_qkvT[k*768 + ob];
        ulonglong2 xv = *(const ulonglong2*)&xs[k];
        u64 w0 = pk2(w2.x, w2.x), w1 = pk2(w2.y, w2.y);
        a0 = fma2(xv.x, w0, a0); a1 = fma2(xv.y, w0, a1);
        b0 = fma2(xv.x, w1, b0); b1 = fma2(xv.y, w1, b1);
    }
    if (kh) { part[p][kh-1][0]=a0; part[p][kh-1][1]=a1; part[p][kh-1][2]=b0; part[p][kh-1][3]=b1; }
    __syncthreads();
    if (kh == 0) {
        #pragma unroll
        for (int m = 0; m < 3; m++) {
            a0 = add2(a0, part[p][m][0]); a1 = add2(a1, part[p][m][1]);
            b0 = add2(b0, part[p][m][2]); b1 = add2(b1, part[p][m][3]);
        }
        float2 bb = *(const float2*)&qkv_b[ob];
        float2 A = up2(a0), B = up2(a1), C = up2(b0), D = up2(b1);
        float r0[4] = { A.x+bb.x, A.y+bb.x, B.x+bb.x, B.y+bb.x };   // col ob, rows 0..3
        float r1[4] = { C.x+bb.y, C.y+bb.y, D.x+bb.y, D.y+bb.y };   // col ob+1
        if (chunk == 0) {
            #pragma unroll
            for (int rr = 0; rr < 4; rr++) {
                g_q[(i0+rr)*DIM + ob]   = r0[rr];
                g_q[(i0+rr)*DIM + ob+1] = r1[rr];
            }
        } else if (chunk == 1) {
            int c0 = ob - 256, jp = i0 >> 1;
            g_k2[c0*256 + jp]       = make_float2(r0[0], r0[1]);
            g_k2[c0*256 + jp + 1]   = make_float2(r0[2], r0[3]);
            g_k2[(c0+1)*256 + jp]   = make_float2(r1[0], r1[1]);
            g_k2[(c0+1)*256 + jp+1] = make_float2(r1[2], r1[3]);
        } else {
            int c0 = ob - 512, jp = i0 >> 1;
            float* base = (float*)g_pvv4;   // float4 [jp][c], v at .z/.w
            *(float2*)&base[((jp  )*256 + c0  )*4 + 2] = make_float2(r0[0], r0[1]);
            *(float2*)&base[((jp+1)*256 + c0  )*4 + 2] = make_float2(r0[2], r0[3]);
            *(float2*)&base[((jp  )*256 + c0+1)*4 + 2] = make_float2(r1[0], r1[1]);
            *(float2*)&base[((jp+1)*256 + c0+1)*4 + 2] = make_float2(r1[2], r1[3]);
        }
    }
}

// ---------------- scores: 2 i x 512 j per block, j-pair x c-half per thread ----------------
// rb2 table comes from __constant__ (LDCU path): no L1 wavefronts for it.
__global__ __launch_bounds__(512, 2) void scores_kernel(const float* __restrict__ rb1_b,
                                                        const float* __restrict__ rb2_b) {
    __shared__ ulonglong2 phq[DIM][2];  // [c] = {ph0_dup, ph1_dup}, {q0s_dup, q1s_dup}
    __shared__ u64 parts[16][256];      // [m][jp] partials from upper c-half
    int i0 = blockIdx.x * 2;
    int t = threadIdx.x;
    int jp = t & 255, ch = t >> 8;      // ch: c-half (warp-uniform)
    const float sc = 0.17677669529663687f;

    if (t < 256) {
        float bh = 0.5f * rb1_b[t];
        float2 pbi = g_pb2[t*256 + (i0 >> 1)];  // {-½pb_i0, -½pb_i1}
        float p0 = bh - pbi.x, p1 = bh - pbi.y;
        float q0 = g_q[i0*DIM + t] * sc, q1 = g_q[(i0+1)*DIM + t] * sc;
        phq[t][0] = make_ulonglong2(pk2(p0, p0), pk2(p1, p1));
        phq[t][1] = make_ulonglong2(pk2(q0, q0), pk2(q1, q1));
    }
    __syncthreads();

    const u64* pbp = (const u64*)g_pb2 + jp;
    const u64* kp  = (const u64*)g_k2 + jp;
    int cbase = ch * 128;

    u64 accb0[8] = {}, accb1[8] = {};
    #pragma unroll
    for (int hs = 0; hs < 4; hs++) {
        u64 s0 = 0, s1 = 0;
        #pragma unroll 4
        for (int c32 = 0; c32 < 32; c32++) {
            int c = cbase + hs*32 + c32;
            u64 pb2v = pbp[c*256];
            u64 k2v  = kp[c*256];
            ulonglong2 pq0 = phq[c][0];
            ulonglong2 pq1 = phq[c][1];
            u64 h20 = add2(pq0.x, pb2v);
            u64 h21 = add2(pq0.y, pb2v);
            float2 f0 = up2(h20), f1 = up2(h21);
            u64 t20 = pk2(ftanh(f0.x), ftanh(f0.y));
            u64 t21 = pk2(ftanh(f1.x), ftanh(f1.y));
            u64 hb0 = fma2(h20, t20, h20);
            u64 hb1 = fma2(h21, t21, h21);
            ulonglong2 rA = *(const ulonglong2*)&c_rb2d[c*8 + 0];
            ulonglong2 rB = *(const ulonglong2*)&c_rb2d[c*8 + 2];
            ulonglong2 rC = *(const ulonglong2*)&c_rb2d[c*8 + 4];
            ulonglong2 rD = *(const ulonglong2*)&c_rb2d[c*8 + 6];
            accb0[0] = fma2(rA.x, hb0, accb0[0]); accb1[0] = fma2(rA.x, hb1, accb1[0]);
            accb0[1] = fma2(rA.y, hb0, accb0[1]); accb1[1] = fma2(rA.y, hb1, accb1[1]);
            accb0[2] = fma2(rB.x, hb0, accb0[2]); accb1[2] = fma2(rB.x, hb1, accb1[2]);
            accb0[3] = fma2(rB.y, hb0, accb0[3]); accb1[3] = fma2(rB.y, hb1, accb1[3]);
            accb0[4] = fma2(rC.x, hb0, accb0[4]); accb1[4] = fma2(rC.x, hb1, accb1[4]);
            accb0[5] = fma2(rC.y, hb0, accb0[5]); accb1[5] = fma2(rC.y, hb1, accb1[5]);
            accb0[6] = fma2(rD.x, hb0, accb0[6]); accb1[6] = fma2(rD.x, hb1, accb1[6]);
            accb0[7] = fma2(rD.y, hb0, accb0[7]); accb1[7] = fma2(rD.y, hb1, accb1[7]);
            s0 = fma2(pq1.x, k2v, s0);
            s1 = fma2(pq1.y, k2v, s1);
        }
        if (ch) { accb0[hs+4] = add2(accb0[hs+4], s0); accb1[hs+4] = add2(accb1[hs+4], s1); }
        else    { accb0[hs]   = add2(accb0[hs],   s0); accb1[hs]   = add2(accb1[hs],   s1); }
    }

    if (ch) {
        #pragma unroll
        for (int m = 0; m < 8; m++) {
            parts[m][jp]   = accb0[m];
            parts[m+8][jp] = accb1[m];
        }
    }
    __syncthreads();
    if (!ch) {
        #pragma unroll
        for (int h = 0; h < NH; h++) {
            u64 v0 = add2(accb0[h], parts[h][jp]);
            u64 v1 = add2(accb1[h], parts[h+8][jp]);
            float rbb = rb2_b[h];
            float2 a0 = up2(v0), a1 = up2(v1);
            *(float2*)&g_scores[(i0*NH + h)*NTOK + 2*jp]     = make_float2(a0.x + rbb, a0.y + rbb);
            *(float2*)&g_scores[((i0+1)*NH + h)*NTOK + 2*jp] = make_float2(a1.x + rbb, a1.y + rbb);
        }
    }
}

// ---------------- attention: j-pair packed ----------------
__global__ __launch_bounds__(256, 5) void attn_kernel(const float* __restrict__ x,
                                                      const float* __restrict__ rv1_b,
                                                      const float* __restrict__ rv2_b) {
    __shared__ ulonglong2 wT2v[NTOK/2*5];   // [jp][h] j-pair weights, stride 10 u64 (20KB)
    __shared__ float whid[NH*DIM];
    __shared__ float sinv[NH];
    u64* wT2 = (u64*)wT2v;
    int i = blockIdx.x, t = threadIdx.x;
    int wid = t >> 5, lane = t & 31;

    { // unnormalized softmax for head wid; store as j-pairs
        const float* row = g_scores + (i*NH + wid)*NTOK;
        float m = -1e30f;
        for (int jj = lane; jj < NTOK; jj += 32) m = fmaxf(m, row[jj]);
        #pragma unroll
        for (int o = 16; o; o >>= 1) m = fmaxf(m, __shfl_xor_sync(0xffffffffu, m, o));
        float s = 0.f;
        for (int jj = lane; jj < NTOK; jj += 32) {
            float e = __expf(row[jj] - m);
            ((float*)wT2)[((jj >> 1)*10 + wid)*2 + (jj & 1)] = e;
            s += e;
        }
        #pragma unroll
        for (int o = 16; o; o >>= 1) s += __shfl_xor_sync(0xffffffffu, s, o);
        if (lane == 0) sinv[wid] = __fdividef(1.0f, s);
    }
    __syncthreads();

    u64 pvih2;
    {
        float2 p2 = *(const float2*)&g_pvv4[(i >> 1)*DIM + t];
        float pvih = 0.5f*rv1_b[t] - ((i & 1) ? p2.y : p2.x);
        pvih2 = pk2(pvih, pvih);
    }
    int hs = t >> 5;
    u64 accW[8] = {};
    u64 accC = 0;
    for (int jjp = 0; jjp < NTOK/2; jjp++) {
        float4 pv4 = g_pvv4[jjp*DIM + t];         // {-½pv_j0, -½pv_j1, v_j0, v_j1}
        u64 pv2 = pk2(pv4.x, pv4.y);
        u64 h2 = add2(pvih2, pv2);
        float2 f = up2(h2);
        u64 t2 = pk2(ftanh(f.x), ftanh(f.y));
        u64 hb2 = fma2(h2, t2, h2);               // {hv_j0, hv_j1}
        const u64* wrow = wT2 + jjp*10;
        ulonglong2 wA = *(const ulonglong2*)&wrow[0];
        ulonglong2 wB = *(const ulonglong2*)&wrow[2];
        ulonglong2 wC = *(const ulonglong2*)&wrow[4];
        ulonglong2 wD = *(const ulonglong2*)&wrow[6];
        accW[0] = fma2(hb2, wA.x, accW[0]); accW[1] = fma2(hb2, wA.y, accW[1]);
        accW[2] = fma2(hb2, wB.x, accW[2]); accW[3] = fma2(hb2, wB.y, accW[3]);
        accW[4] = fma2(hb2, wC.x, accW[4]); accW[5] = fma2(hb2, wC.y, accW[5]);
        accW[6] = fma2(hb2, wD.x, accW[6]); accW[7] = fma2(hb2, wD.y, accW[7]);
        u64 v2 = pk2(pv4.z, pv4.w);
        accC = fma2(wrow[hs], v2, accC);          // warp-uniform LDS broadcast
    }
    #pragma unroll
    for (int h = 0; h < NH; h++) {
        float2 v = up2(accW[h]);
        whid[h*DIM + t] = (v.x + v.y) * sinv[h];
    }
    float accCf;
    { float2 fc = up2(accC); accCf = (fc.x + fc.y) * sinv[hs]; }
    __syncthreads();

    u64 accP2 = 0;
    #pragma unroll 4
    for (int cp = 0; cp < DIM/2; cp++) {
        u64 wh = *(const u64*)&whid[hs*DIM + 2*cp];   // broadcast pair
        float2 rv = g_rv2p[cp*DIM + t];
        accP2 = fma2(wh, pk2(rv.x, rv.y), accP2);
    }
    float2 fp = up2(accP2);
    g_resid[i*DIM + t] = x[i*DIM + t] + accCf + fp.x + fp.y + rv2_b[t];
}

// ---------------- FFN up (LN2 fused): 4 rows, 2 cols/thread, k-split 4 ----------------
__global__ __launch_bounds__(512) void ffn1_kernel(const float* __restrict__ ln2_w,
                                                   const float* __restrict__ ln2_b,
                                                   const float* __restrict__ b1,
                                                   const float* __restrict__ b2) {
    __shared__ float4 xs[DIM];
    __shared__ float2 red2[4][4];
    __shared__ u64 parta[128][3][4];
    __shared__ u64 partc[128][3][4];
    int t = threadIdx.x;
    int i0 = blockIdx.x * 4, chunk = blockIdx.y;
    block_ln4(g_resid, i0, ln2_w, ln2_b, xs, red2);

    int p = t & 127, kh = t >> 7;
    int o = chunk*256 + p*2;
    int ocl = (o <= HIDN-2) ? o : (HIDN-2);
    u64 a0=0, a1=0, a2=0, a3=0, c0=0, c1=0, c2=0, c3=0;
    int kbeg = kh * 64;
    #pragma unroll 4
    for (int kk = 0; kk < 64; kk++) {
        int k = kbeg + kk;
        float2 u2 = *(const float2*)&g_w1T[k*HIDN + ocl];
        float2 v2 = *(const float2*)&g_w2T[k*HIDN + ocl];
        ulonglong2 xv = *(const ulonglong2*)&xs[k];
        u64 u0 = pk2(u2.x,u2.x), u1 = pk2(u2.y,u2.y);
        u64 v0 = pk2(v2.x,v2.x), v1 = pk2(v2.y,v2.y);
        a0 = fma2(xv.x,u0,a0); a1 = fma2(xv.y,u0,a1);
        a2 = fma2(xv.x,u1,a2); a3 = fma2(xv.y,u1,a3);
        c0 = fma2(xv.x,v0,c0); c1 = fma2(xv.y,v0,c1);
        c2 = fma2(xv.x,v1,c2); c3 = fma2(xv.y,v1,c3);
    }
    if (kh) {
        parta[p][kh-1][0]=a0; parta[p][kh-1][1]=a1; parta[p][kh-1][2]=a2; parta[p][kh-1][3]=a3;
        partc[p][kh-1][0]=c0; partc[p][kh-1][1]=c1; partc[p][kh-1][2]=c2; partc[p][kh-1][3]=c3;
    }
    __syncthreads();
    if (kh == 0 && o < HIDN) {
        #pragma unroll
        for (int m = 0; m < 3; m++) {
            a0 = add2(a0, parta[p][m][0]); a1 = add2(a1, parta[p][m][1]);
            a2 = add2(a2, parta[p][m][2]); a3 = add2(a3, parta[p][m][3]);
            c0 = add2(c0, partc[p][m][0]); c1 = add2(c1, partc[p][m][1]);
            c2 = add2(c2, partc[p][m][2]); c3 = add2(c3, partc[p][m][3]);
        }
        float2 A0 = up2(a0), A1 = up2(a1), A2 = up2(a2), A3 = up2(a3);
        float2 C0 = up2(c0), C1 = up2(c1), C2 = up2(c2), C3 = up2(c3);
        float bb10 = b1[o], bb11 = b1[o+1], bb20 = b2[o], bb21 = b2[o+1];
        g_gate[(i0+0)*HIDN + o]   = fsilu(A0.x + bb10) * (C0.x + bb20);
        g_gate[(i0+1)*HIDN + o]   = fsilu(A0.y + bb10) * (C0.y + bb20);
        g_gate[(i0+2)*HIDN + o]   = fsilu(A1.x + bb10) * (C1.x + bb20);
        g_gate[(i0+3)*HIDN + o]   = fsilu(A1.y + bb10) * (C1.y + bb20);
        g_gate[(i0+0)*HIDN + o+1] = fsilu(A2.x + bb11) * (C2.x + bb21);
        g_gate[(i0+1)*HIDN + o+1] = fsilu(A2.y + bb11) * (C2.y + bb21);
        g_gate[(i0+2)*HIDN + o+1] = fsilu(A3.x + bb11) * (C3.x + bb21);
        g_gate[(i0+3)*HIDN + o+1] = fsilu(A3.y + bb11) * (C3.y + bb21);
    }
}

// ---------------- FFN down + residual: 2 rows, 2 cols/thread, o-split 4 ----------------
__global__ __launch_bounds__(512) void ffn2_kernel(const float* __restrict__ b3,
                                                   float* __restrict__ out) {
    __shared__ float2 gs[HIDN];
    __shared__ u64 part[128][3][2];
    int i0 = blockIdx.x * 2, t = threadIdx.x;
    int p = t & 127, oh = t >> 7;
    for (int idx = t; idx < HIDN; idx += 512)
        gs[idx] = make_float2(g_gate[i0*HIDN + idx], g_gate[(i0+1)*HIDN + idx]);
    __syncthreads();
    const int obeg[5] = {0, 171, 342, 512, 682};
    int os = obeg[oh], oe = obeg[oh+1];
    int d = p*2;
    u64 acc0 = 0, acc1 = 0;
    for (int o = os; o < oe; o++) {
        float2 w = *(const float2*)&g_w3T[o*DIM + d];
        u64 g2 = *(const u64*)&gs[o];
        acc0 = fma2(g2, pk2(w.x, w.x), acc0);
        acc1 = fma2(g2, pk2(w.y, w.y), acc1);
    }
    if (oh) { part[p][oh-1][0] = acc0; part[p][oh-1][1] = acc1; }
    __syncthreads();
    if (oh == 0) {
        #pragma unroll
        for (int m = 0; m < 3; m++) {
            acc0 = add2(acc0, part[p][m][0]);
            acc1 = add2(acc1, part[p][m][1]);
        }
        float2 A = up2(acc0), B = up2(acc1);
        float2 bb = *(const float2*)&b3[d];
        out[i0*DIM + d]       = g_resid[i0*DIM + d]       + A.x + bb.x;
        out[(i0+1)*DIM + d]   = g_resid[(i0+1)*DIM + d]   + A.y + bb.x;
        out[i0*DIM + d+1]     = g_resid[i0*DIM + d+1]     + B.x + bb.y;
        out[(i0+1)*DIM + d+1] = g_resid[(i0+1)*DIM + d+1] + B.y + bb.y;
    }
}

// ---------------- launch ----------------
extern "C" void kernel_launch(void* const* d_in, const int* in_sizes, int n_in,
                              void* d_out, int out_size) {
    const float* x      = (const float*)d_in[0];
    const float* coords = (const float*)d_in[1];
    const float* ln1_w  = (const float*)d_in[2];
    const float* ln1_b  = (const float*)d_in[3];
    const float* ln2_w  = (const float*)d_in[4];
    const float* ln2_b  = (const float*)d_in[5];
    const float* qkv_w  = (const float*)d_in[6];
    const float* qkv_b  = (const float*)d_in[7];
    const float* rb1_w  = (const float*)d_in[8];
    const float* rb1_b  = (const float*)d_in[9];
    const float* rb2_w  = (const float*)d_in[10];
    const float* rb2_b  = (const float*)d_in[11];
    const float* rv1_w  = (const float*)d_in[12];
    const float* rv1_b  = (const float*)d_in[13];
    const float* rv2_w  = (const float*)d_in[14];
    const float* rv2_b  = (const float*)d_in[15];
    const float* w1     = (const float*)d_in[16];
    const float* b1     = (const float*)d_in[17];
    const float* w2     = (const float*)d_in[18];
    const float* b2     = (const float*)d_in[19];
    const float* w3     = (const float*)d_in[20];
    const float* b3     = (const float*)d_in[21];
    float* out = (float*)d_out;

    prep_p<<<512, 256>>>(coords, rb1_w, rv1_w, rb2_w, rv2_w);
    // stage the duplicated rb2 table into the constant bank (graph-capturable async D2D)
    {
        void* src = nullptr;
        cudaGetSymbolAddress(&src, g_rb2d);
        cudaMemcpyToSymbolAsync(c_rb2d, src, DIM*NH*sizeof(u64), 0,
                                cudaMemcpyDeviceToDevice, 0);
    }
    tr_kernel<<<dim3(22, 24, 4), dim3(32, 8)>>>(qkv_w, w1, w2, w3);
    qkv_kernel<<<dim3(128, 3), 512>>>(x, ln1_w, ln1_b, qkv_b);
    scores_kernel<<<256, 512>>>(rb1_b, rb2_b);
    attn_kernel<<<NTOK, 256>>>(x, rv1_b, rv2_b);
    ffn1_kernel<<<dim3(128, 3), 512>>>(ln2_w, ln2_b, b1, b2);
    ffn2_kernel<<<256, 512>>>(b3, out);
}

// round 13
// speedup vs baseline: 1.2150x; 1.0453x over previous
#include <cuda_runtime.h>
#include <math.h>

#define NTOK 512
#define DIM 256
#define NH 8
#define HDIM 32
#define HIDN 682

typedef unsigned long long u64;

__device__ __forceinline__ u64 pk2(float lo, float hi) {
    u64 r; asm("mov.b64 %0, {%1,%2};" : "=l"(r) : "f"(lo), "f"(hi)); return r;
}
__device__ __forceinline__ float2 up2(u64 v) {
    float2 f; asm("mov.b64 {%0,%1}, %2;" : "=f"(f.x), "=f"(f.y) : "l"(v)); return f;
}
__device__ __forceinline__ u64 fma2(u64 a, u64 b, u64 c) {
    u64 d; asm("fma.rn.f32x2 %0, %1, %2, %3;" : "=l"(d) : "l"(a), "l"(b), "l"(c)); return d;
}
__device__ __forceinline__ u64 add2(u64 a, u64 b) {
    u64 d; asm("add.rn.f32x2 %0, %1, %2;" : "=l"(d) : "l"(a), "l"(b)); return d;
}
__device__ __forceinline__ float ftanh(float x) {
    float t; asm("tanh.approx.f32 %0, %1;" : "=f"(t) : "f"(x)); return t;
}
__device__ __forceinline__ float fsilu(float x) {
    float h = 0.5f * x;
    return fmaf(h, ftanh(h), h);
}

// ---------------- scratch ----------------
__device__ float g_q[NTOK*DIM];
__device__ float2 g_pb2[DIM*NTOK/2];   // [c][jp] = {-0.5*pb_{2jp}, -0.5*pb_{2jp+1}}
__device__ float2 g_k2[DIM*NTOK/2];    // [c][jp] = {k_{2jp}, k_{2jp+1}}
__device__ float4 g_pvv4[NTOK/2*DIM];  // [jp][c] = {-0.5pv_j0, -0.5pv_j1, v_j0, v_j1}
__device__ float2 g_rv2p[DIM/2*DIM];   // [cp][o] = {rv2T[2cp][o], rv2T[2cp+1][o]}
__device__ u64   g_rb2d[DIM*NH];       // [c][h] duplicated pairs
__device__ float g_qkvT[DIM*3*DIM];    // [k][o]
__device__ float g_w1T[DIM*HIDN];      // [k][o]
__device__ float g_w2T[DIM*HIDN];
__device__ float g_w3T[HIDN*DIM];      // [o][d]
__device__ float g_scores[NTOK*NH*NTOK]; // [i][h][j]
__device__ float g_resid[NTOK*DIM];
__device__ float g_gate[NTOK*HIDN];

// ---------------- setup: prep (blocks 0..511) + transposes (blocks 512..1231) ----------------
__global__ void setup_kernel(const float* __restrict__ coords,
                             const float* __restrict__ rb1_w,
                             const float* __restrict__ rv1_w,
                             const float* __restrict__ rb2_w,
                             const float* __restrict__ rv2_w,
                             const float* __restrict__ qkv_w,
                             const float* __restrict__ w1,
                             const float* __restrict__ w2,
                             const float* __restrict__ w3) {
    __shared__ float tile[32][33];
    int b = blockIdx.x;
    int t = threadIdx.x;
    if (b < 512) {
        int idx = b * 256 + t;   // 131072
        {
            int c = idx >> 9, n = idx & 511;        // [c][n]
            float x0 = coords[n*3+0], x1 = coords[n*3+1], x2 = coords[n*3+2];
            float pb = x0*rb1_w[c*3+0] + x1*rb1_w[c*3+1] + x2*rb1_w[c*3+2];
            ((float*)g_pb2)[idx] = -0.5f * pb;
        }
        if (idx < 65536) {                           // pvv4 .x/.y
            int jp = idx >> 8, c = idx & 255;
            int j0 = 2*jp, j1 = j0 + 1;
            float w0 = rv1_w[c*3+0], w1v = rv1_w[c*3+1], w2v = rv1_w[c*3+2];
            float pv0 = coords[j0*3+0]*w0 + coords[j0*3+1]*w1v + coords[j0*3+2]*w2v;
            float pv1 = coords[j1*3+0]*w0 + coords[j1*3+1]*w1v + coords[j1*3+2]*w2v;
            *(float2*)&g_pvv4[idx] = make_float2(-0.5f*pv0, -0.5f*pv1);
        }
        if (idx < 32768) {                           // rv2 c-pair
            int o = idx >> 7, cp = idx & 127;
            float2 rv = *(const float2*)&rv2_w[o*DIM + 2*cp];
            g_rv2p[cp*DIM + o] = rv;
        }
        if (idx < NH*DIM) {
            int h = idx / DIM, c = idx % DIM;
            float r = rb2_w[idx];
            g_rb2d[c*NH + h] = pk2(r, r);
        }
        return;
    }
    // ---- transpose part ----
    int tb = b - 512;
    const float* src; float* dst; int R, C, bxi, byi;
    if (tb < 192)      { src = qkv_w; dst = g_qkvT; R = 768;  C = 256;  bxi = tb & 7;  byi = tb >> 3; }
    else if (tb < 368) { int r = tb-192; src = w1; dst = g_w1T; R = HIDN; C = 256; bxi = r & 7; byi = r >> 3; }
    else if (tb < 544) { int r = tb-368; src = w2; dst = g_w2T; R = HIDN; C = 256; bxi = r & 7; byi = r >> 3; }
    else               { int r = tb-544; src = w3; dst = g_w3T; R = 256;  C = HIDN; bxi = r % 22; byi = r / 22; }
    int bx = bxi * 32, by = byi * 32;
    if (bx >= C || by >= R) return;
    int tx = t & 31, ty = t >> 5;
    #pragma unroll
    for (int dy = ty; dy < 32; dy += 8) {
        int r = by + dy, cc = bx + tx;
        if (r < R && cc < C) tile[dy][tx] = src[r*C + cc];
    }
    __syncthreads();
    #pragma unroll
    for (int dy = ty; dy < 32; dy += 8) {
        int r = bx + dy, cc = by + tx;   // dst is [C][R]
        if (r < C && cc < R) dst[r*R + cc] = tile[tx][dy];
    }
}

// ---- in-block LayerNorm of 4 rows into xs[c] (float4 over rows) ----
__device__ __forceinline__ void block_ln4(const float* __restrict__ src, int i0,
                                          const float* __restrict__ lnw,
                                          const float* __restrict__ lnb,
                                          float4* xs, float2 (*red2)[4]) {
    int t = threadIdx.x;
    int lane = t & 31, r = t >> 7, wir = (t >> 5) & 3;
    int cc = (t & 127) * 2;
    float2 xv = *(const float2*)&src[(i0+r)*DIM + cc];
    float s1 = xv.x + xv.y;
    float s2 = fmaf(xv.x, xv.x, xv.y*xv.y);
    #pragma unroll
    for (int o = 16; o; o >>= 1) {
        s1 += __shfl_xor_sync(0xffffffffu, s1, o);
        s2 += __shfl_xor_sync(0xffffffffu, s2, o);
    }
    if (lane == 0) red2[r][wir] = make_float2(s1, s2);
    __syncthreads();
    float S1 = red2[r][0].x + red2[r][1].x + red2[r][2].x + red2[r][3].x;
    float S2 = red2[r][0].y + red2[r][1].y + red2[r][2].y + red2[r][3].y;
    float mean = S1 * (1.0f/256.0f);
    float var  = S2 * (1.0f/256.0f) - mean*mean;
    float inv  = rsqrtf(var + 1e-5f);
    float2 wv = *(const float2*)&lnw[cc];
    float2 bv = *(const float2*)&lnb[cc];
    ((float*)&xs[cc])[r]   = (xv.x - mean)*inv*wv.x + bv.x;
    ((float*)&xs[cc+1])[r] = (xv.y - mean)*inv*wv.y + bv.y;
    __syncthreads();
}

// ---------------- QKV (LN1 fused): 4 rows, 256-col chunk, 2 cols/thread, k-split 4 ----------------
__global__ __launch_bounds__(512) void qkv_kernel(const float* __restrict__ x,
                                                  const float* __restrict__ ln1_w,
                                                  const float* __restrict__ ln1_b,
                                                  const float* __restrict__ qkv_b) {
    __shared__ float4 xs[DIM];
    __shared__ float2 red2[4][4];
    __shared__ u64 part[128][3][4];
    int t = threadIdx.x;
    int i0 = blockIdx.x * 4, chunk = blockIdx.y;
    block_ln4(x, i0, ln1_w, ln1_b, xs, red2);

    int p = t & 127, kh = t >> 7;
    int ob = chunk*256 + p*2;
    u64 a0 = 0, a1 = 0, b0 = 0, b1 = 0;
    int kbeg = kh * 64;
    #pragma unroll 4
    for (int kk = 0; kk < 64; kk++) {
        int k = kbeg + kk;
        float2 w2 = *(const float2*)&g_qkvT[k*768 + ob];
        ulonglong2 xv = *(const ulonglong2*)&xs[k];
        u64 w0 = pk2(w2.x, w2.x), w1 = pk2(w2.y, w2.y);
        a0 = fma2(xv.x, w0, a0); a1 = fma2(xv.y, w0, a1);
        b0 = fma2(xv.x, w1, b0); b1 = fma2(xv.y, w1, b1);
    }
    if (kh) { part[p][kh-1][0]=a0; part[p][kh-1][1]=a1; part[p][kh-1][2]=b0; part[p][kh-1][3]=b1; }
    __syncthreads();
    if (kh == 0) {
        #pragma unroll
        for (int m = 0; m < 3; m++) {
            a0 = add2(a0, part[p][m][0]); a1 = add2(a1, part[p][m][1]);
            b0 = add2(b0, part[p][m][2]); b1 = add2(b1, part[p][m][3]);
        }
        float2 bb = *(const float2*)&qkv_b[ob];
        float2 A = up2(a0), B = up2(a1), C = up2(b0), D = up2(b1);
        float r0[4] = { A.x+bb.x, A.y+bb.x, B.x+bb.x, B.y+bb.x };
        float r1[4] = { C.x+bb.y, C.y+bb.y, D.x+bb.y, D.y+bb.y };
        if (chunk == 0) {
            #pragma unroll
            for (int rr = 0; rr < 4; rr++) {
                g_q[(i0+rr)*DIM + ob]   = r0[rr];
                g_q[(i0+rr)*DIM + ob+1] = r1[rr];
            }
        } else if (chunk == 1) {
            int c0 = ob - 256, jp = i0 >> 1;
            g_k2[c0*256 + jp]       = make_float2(r0[0], r0[1]);
            g_k2[c0*256 + jp + 1]   = make_float2(r0[2], r0[3]);
            g_k2[(c0+1)*256 + jp]   = make_float2(r1[0], r1[1]);
            g_k2[(c0+1)*256 + jp+1] = make_float2(r1[2], r1[3]);
        } else {
            int c0 = ob - 512, jp = i0 >> 1;
            float* base = (float*)g_pvv4;   // float4 [jp][c], v at .z/.w
            *(float2*)&base[((jp  )*256 + c0  )*4 + 2] = make_float2(r0[0], r0[1]);
            *(float2*)&base[((jp+1)*256 + c0  )*4 + 2] = make_float2(r0[2], r0[3]);
            *(float2*)&base[((jp  )*256 + c0+1)*4 + 2] = make_float2(r1[0], r1[1]);
            *(float2*)&base[((jp+1)*256 + c0+1)*4 + 2] = make_float2(r1[2], r1[3]);
        }
    }
}

// ---------------- scores: 2 i x 512 j per block, j-pair x c-half per thread ----------------
__global__ __launch_bounds__(512, 2) void scores_kernel(const float* __restrict__ rb1_b,
                                                        const float* __restrict__ rb2_b) {
    __shared__ ulonglong2 phq[DIM][2];  // [c] = {ph0_dup, ph1_dup}, {q0s_dup, q1s_dup}
    __shared__ u64 rbs[DIM*NH];         // 16KB duplicated rb2
    __shared__ u64 parts[16][256];      // [m][jp] partials from upper c-half
    int i0 = blockIdx.x * 2;
    int t = threadIdx.x;
    int jp = t & 255, ch = t >> 8;
    const float sc = 0.17677669529663687f;

    if (t < 256) {
        float bh = 0.5f * rb1_b[t];
        float2 pbi = g_pb2[t*256 + (i0 >> 1)];
        float p0 = bh - pbi.x, p1 = bh - pbi.y;
        float q0 = g_q[i0*DIM + t] * sc, q1 = g_q[(i0+1)*DIM + t] * sc;
        phq[t][0] = make_ulonglong2(pk2(p0, p0), pk2(p1, p1));
        phq[t][1] = make_ulonglong2(pk2(q0, q0), pk2(q1, q1));
    }
    #pragma unroll
    for (int m = 0; m < 4; m++) rbs[m*512 + t] = g_rb2d[m*512 + t];
    __syncthreads();

    const u64* pbp = (const u64*)g_pb2 + jp;
    const u64* kp  = (const u64*)g_k2 + jp;
    int cbase = ch * 128;

    u64 accb0[8] = {}, accb1[8] = {};
    #pragma unroll
    for (int hs = 0; hs < 4; hs++) {
        u64 s0 = 0, s1 = 0;
        #pragma unroll 4
        for (int c32 = 0; c32 < 32; c32++) {
            int c = cbase + hs*32 + c32;
            u64 pb2v = pbp[c*256];
            u64 k2v  = kp[c*256];
            ulonglong2 pq0 = phq[c][0];
            ulonglong2 pq1 = phq[c][1];
            u64 h20 = add2(pq0.x, pb2v);
            u64 h21 = add2(pq0.y, pb2v);
            float2 f0 = up2(h20), f1 = up2(h21);
            u64 t20 = pk2(ftanh(f0.x), ftanh(f0.y));
            u64 t21 = pk2(ftanh(f1.x), ftanh(f1.y));
            u64 hb0 = fma2(h20, t20, h20);
            u64 hb1 = fma2(h21, t21, h21);
            ulonglong2 rA = *(const ulonglong2*)&rbs[c*8 + 0];
            ulonglong2 rB = *(const ulonglong2*)&rbs[c*8 + 2];
            ulonglong2 rC = *(const ulonglong2*)&rbs[c*8 + 4];
            ulonglong2 rD = *(const ulonglong2*)&rbs[c*8 + 6];
            accb0[0] = fma2(rA.x, hb0, accb0[0]); accb1[0] = fma2(rA.x, hb1, accb1[0]);
            accb0[1] = fma2(rA.y, hb0, accb0[1]); accb1[1] = fma2(rA.y, hb1, accb1[1]);
            accb0[2] = fma2(rB.x, hb0, accb0[2]); accb1[2] = fma2(rB.x, hb1, accb1[2]);
            accb0[3] = fma2(rB.y, hb0, accb0[3]); accb1[3] = fma2(rB.y, hb1, accb1[3]);
            accb0[4] = fma2(rC.x, hb0, accb0[4]); accb1[4] = fma2(rC.x, hb1, accb1[4]);
            accb0[5] = fma2(rC.y, hb0, accb0[5]); accb1[5] = fma2(rC.y, hb1, accb1[5]);
            accb0[6] = fma2(rD.x, hb0, accb0[6]); accb1[6] = fma2(rD.x, hb1, accb1[6]);
            accb0[7] = fma2(rD.y, hb0, accb0[7]); accb1[7] = fma2(rD.y, hb1, accb1[7]);
            s0 = fma2(pq1.x, k2v, s0);
            s1 = fma2(pq1.y, k2v, s1);
        }
        if (ch) { accb0[hs+4] = add2(accb0[hs+4], s0); accb1[hs+4] = add2(accb1[hs+4], s1); }
        else    { accb0[hs]   = add2(accb0[hs],   s0); accb1[hs]   = add2(accb1[hs],   s1); }
    }

    if (ch) {
        #pragma unroll
        for (int m = 0; m < 8; m++) {
            parts[m][jp]   = accb0[m];
            parts[m+8][jp] = accb1[m];
        }
    }
    __syncthreads();
    if (!ch) {
        #pragma unroll
        for (int h = 0; h < NH; h++) {
            u64 v0 = add2(accb0[h], parts[h][jp]);
            u64 v1 = add2(accb1[h], parts[h+8][jp]);
            float rbb = rb2_b[h];
            float2 a0 = up2(v0), a1 = up2(v1);
            *(float2*)&g_scores[(i0*NH + h)*NTOK + 2*jp]     = make_float2(a0.x + rbb, a0.y + rbb);
            *(float2*)&g_scores[((i0+1)*NH + h)*NTOK + 2*jp] = make_float2(a1.x + rbb, a1.y + rbb);
        }
    }
}

// ---------------- attention: 2 i per block, 512 threads = (c, j-half) ----------------
#define WTS 18   // u64 stride per jp in wT
__global__ __launch_bounds__(512, 2) void attn_kernel(const float* __restrict__ x,
                                                      const float* __restrict__ rv1_b,
                                                      const float* __restrict__ rv2_b) {
    __shared__ u64 wT[256*WTS];            // [jp][i*8+h] j-pair weights; ALSO reused as parts
    __shared__ float whid[2][NH][DIM];     // 16KB
    __shared__ float accs[2][DIM];
    __shared__ float sinv[2][NH];
    int i0 = blockIdx.x * 2;
    int t = threadIdx.x;
    int wid = t >> 5, lane = t & 31;
    int c = t & 255, jh = t >> 8;

    { // softmax: 16 warps, warp r -> (i = r>>3, h = r&7)
        int ii = wid >> 3, h = wid & 7;
        const float* row = g_scores + ((i0+ii)*NH + h)*NTOK;
        float m = -1e30f;
        for (int jj = lane; jj < NTOK; jj += 32) m = fmaxf(m, row[jj]);
        #pragma unroll
        for (int o = 16; o; o >>= 1) m = fmaxf(m, __shfl_xor_sync(0xffffffffu, m, o));
        float s = 0.f;
        for (int jj = lane; jj < NTOK; jj += 32) {
            float e = __expf(row[jj] - m);
            ((float*)wT)[((jj >> 1)*WTS + ii*8 + h)*2 + (jj & 1)] = e;
            s += e;
        }
        #pragma unroll
        for (int o = 16; o; o >>= 1) s += __shfl_xor_sync(0xffffffffu, s, o);
        if (lane == 0) sinv[ii][h] = __fdividef(1.0f, s);
    }
    __syncthreads();

    u64 pvih2_0, pvih2_1;
    {
        float2 p2 = *(const float2*)&g_pvv4[(i0 >> 1)*DIM + c];  // {-½pv_i0, -½pv_i1}
        float bh = 0.5f * rv1_b[c];
        float v0 = bh - p2.x, v1 = bh - p2.y;
        pvih2_0 = pk2(v0, v0);
        pvih2_1 = pk2(v1, v1);
    }
    u64 accW[16] = {};
    u64 accC0 = 0, accC1 = 0;
    int hs = c >> 5;
    int jbeg = jh * 128, jend = jbeg + 128;
    for (int jjp = jbeg; jjp < jend; jjp++) {
        float4 pv4 = g_pvv4[jjp*DIM + c];          // {-½pv_j0, -½pv_j1, v_j0, v_j1}
        u64 pv2 = pk2(pv4.x, pv4.y);
        u64 h20 = add2(pvih2_0, pv2);
        u64 h21 = add2(pvih2_1, pv2);
        float2 f0 = up2(h20), f1 = up2(h21);
        u64 t20 = pk2(ftanh(f0.x), ftanh(f0.y));
        u64 t21 = pk2(ftanh(f1.x), ftanh(f1.y));
        u64 hb0 = fma2(h20, t20, h20);
        u64 hb1 = fma2(h21, t21, h21);
        const u64* wrow = wT + jjp*WTS;
        ulonglong2 wA = *(const ulonglong2*)&wrow[0];
        ulonglong2 wB = *(const ulonglong2*)&wrow[2];
        ulonglong2 wC = *(const ulonglong2*)&wrow[4];
        ulonglong2 wD = *(const ulonglong2*)&wrow[6];
        ulonglong2 wE = *(const ulonglong2*)&wrow[8];
        ulonglong2 wF = *(const ulonglong2*)&wrow[10];
        ulonglong2 wG = *(const ulonglong2*)&wrow[12];
        ulonglong2 wH = *(const ulonglong2*)&wrow[14];
        accW[0]  = fma2(hb0, wA.x, accW[0]);  accW[1]  = fma2(hb0, wA.y, accW[1]);
        accW[2]  = fma2(hb0, wB.x, accW[2]);  accW[3]  = fma2(hb0, wB.y, accW[3]);
        accW[4]  = fma2(hb0, wC.x, accW[4]);  accW[5]  = fma2(hb0, wC.y, accW[5]);
        accW[6]  = fma2(hb0, wD.x, accW[6]);  accW[7]  = fma2(hb0, wD.y, accW[7]);
        accW[8]  = fma2(hb1, wE.x, accW[8]);  accW[9]  = fma2(hb1, wE.y, accW[9]);
        accW[10] = fma2(hb1, wF.x, accW[10]); accW[11] = fma2(hb1, wF.y, accW[11]);
        accW[12] = fma2(hb1, wG.x, accW[12]); accW[13] = fma2(hb1, wG.y, accW[13]);
        accW[14] = fma2(hb1, wH.x, accW[14]); accW[15] = fma2(hb1, wH.y, accW[15]);
        u64 v2 = pk2(pv4.z, pv4.w);
        accC0 = fma2(wrow[hs], v2, accC0);        // uniform LDS broadcast
        accC1 = fma2(wrow[8 + hs], v2, accC1);
    }
    __syncthreads();   // all wT reads done before aliasing as parts

    u64* parts = wT;   // [m][c]: 18*256 u64 = wT size
    if (jh) {
        #pragma unroll
        for (int m = 0; m < 16; m++) parts[m*256 + c] = accW[m];
        parts[16*256 + c] = accC0;
        parts[17*256 + c] = accC1;
    }
    __syncthreads();
    if (!jh) {
        #pragma unroll
        for (int m = 0; m < 16; m++) {
            u64 v = add2(accW[m], parts[m*256 + c]);
            float2 f = up2(v);
            int ii = m >> 3, h = m & 7;
            whid[ii][h][c] = (f.x + f.y) * sinv[ii][h];
        }
        {
            u64 v = add2(accC0, parts[16*256 + c]);
            float2 f = up2(v);
            accs[0][c] = (f.x + f.y) * sinv[0][hs];
        }
        {
            u64 v = add2(accC1, parts[17*256 + c]);
            float2 f = up2(v);
            accs[1][c] = (f.x + f.y) * sinv[1][hs];
        }
    }
    __syncthreads();

    // rv2 phase: thread (o = c, i = jh)
    u64 accP2 = 0;
    #pragma unroll 4
    for (int cp = 0; cp < DIM/2; cp++) {
        u64 wh = *(const u64*)&whid[jh][hs][2*cp];   // uniform broadcast
        float2 rv = g_rv2p[cp*DIM + c];
        accP2 = fma2(wh, pk2(rv.x, rv.y), accP2);
    }
    float2 fp = up2(accP2);
    int i = i0 + jh;
    g_resid[i*DIM + c] = x[i*DIM + c] + accs[jh][c] + fp.x + fp.y + rv2_b[c];
}

// ---------------- FFN up (LN2 fused): 4 rows, 2 cols/thread, k-split 4 ----------------
__global__ __launch_bounds__(512) void ffn1_kernel(const float* __restrict__ ln2_w,
                                                   const float* __restrict__ ln2_b,
                                                   const float* __restrict__ b1,
                                                   const float* __restrict__ b2) {
    __shared__ float4 xs[DIM];
    __shared__ float2 red2[4][4];
    __shared__ u64 parta[128][3][4];
    __shared__ u64 partc[128][3][4];
    int t = threadIdx.x;
    int i0 = blockIdx.x * 4, chunk = blockIdx.y;
    block_ln4(g_resid, i0, ln2_w, ln2_b, xs, red2);

    int p = t & 127, kh = t >> 7;
    int o = chunk*256 + p*2;
    int ocl = (o <= HIDN-2) ? o : (HIDN-2);
    u64 a0=0, a1=0, a2=0, a3=0, c0=0, c1=0, c2=0, c3=0;
    int kbeg = kh * 64;
    #pragma unroll 4
    for (int kk = 0; kk < 64; kk++) {
        int k = kbeg + kk;
        float2 u2 = *(const float2*)&g_w1T[k*HIDN + ocl];
        float2 v2 = *(const float2*)&g_w2T[k*HIDN + ocl];
        ulonglong2 xv = *(const ulonglong2*)&xs[k];
        u64 u0 = pk2(u2.x,u2.x), u1 = pk2(u2.y,u2.y);
        u64 v0 = pk2(v2.x,v2.x), v1 = pk2(v2.y,v2.y);
        a0 = fma2(xv.x,u0,a0); a1 = fma2(xv.y,u0,a1);
        a2 = fma2(xv.x,u1,a2); a3 = fma2(xv.y,u1,a3);
        c0 = fma2(xv.x,v0,c0); c1 = fma2(xv.y,v0,c1);
        c2 = fma2(xv.x,v1,c2); c3 = fma2(xv.y,v1,c3);
    }
    if (kh) {
        parta[p][kh-1][0]=a0; parta[p][kh-1][1]=a1; parta[p][kh-1][2]=a2; parta[p][kh-1][3]=a3;
        partc[p][kh-1][0]=c0; partc[p][kh-1][1]=c1; partc[p][kh-1][2]=c2; partc[p][kh-1][3]=c3;
    }
    __syncthreads();
    if (kh == 0 && o < HIDN) {
        #pragma unroll
        for (int m = 0; m < 3; m++) {
            a0 = add2(a0, parta[p][m][0]); a1 = add2(a1, parta[p][m][1]);
            a2 = add2(a2, parta[p][m][2]); a3 = add2(a3, parta[p][m][3]);
            c0 = add2(c0, partc[p][m][0]); c1 = add2(c1, partc[p][m][1]);
            c2 = add2(c2, partc[p][m][2]); c3 = add2(c3, partc[p][m][3]);
        }
        float2 A0 = up2(a0), A1 = up2(a1), A2 = up2(a2), A3 = up2(a3);
        float2 C0 = up2(c0), C1 = up2(c1), C2 = up2(c2), C3 = up2(c3);
        float bb10 = b1[o], bb11 = b1[o+1], bb20 = b2[o], bb21 = b2[o+1];
        g_gate[(i0+0)*HIDN + o]   = fsilu(A0.x + bb10) * (C0.x + bb20);
        g_gate[(i0+1)*HIDN + o]   = fsilu(A0.y + bb10) * (C0.y + bb20);
        g_gate[(i0+2)*HIDN + o]   = fsilu(A1.x + bb10) * (C1.x + bb20);
        g_gate[(i0+3)*HIDN + o]   = fsilu(A1.y + bb10) * (C1.y + bb20);
        g_gate[(i0+0)*HIDN + o+1] = fsilu(A2.x + bb11) * (C2.x + bb21);
        g_gate[(i0+1)*HIDN + o+1] = fsilu(A2.y + bb11) * (C2.y + bb21);
        g_gate[(i0+2)*HIDN + o+1] = fsilu(A3.x + bb11) * (C3.x + bb21);
        g_gate[(i0+3)*HIDN + o+1] = fsilu(A3.y + bb11) * (C3.y + bb21);
    }
}

// ---------------- FFN down + residual: 2 rows, 2 cols/thread, o-split 4 ----------------
__global__ __launch_bounds__(512) void ffn2_kernel(const float* __restrict__ b3,
                                                   float* __restrict__ out) {
    __shared__ float2 gs[HIDN];
    __shared__ u64 part[128][3][2];
    int i0 = blockIdx.x * 2, t = threadIdx.x;
    int p = t & 127, oh = t >> 7;
    for (int idx = t; idx < HIDN; idx += 512)
        gs[idx] = make_float2(g_gate[i0*HIDN + idx], g_gate[(i0+1)*HIDN + idx]);
    __syncthreads();
    const int obeg[5] = {0, 171, 342, 512, 682};
    int os = obeg[oh], oe = obeg[oh+1];
    int d = p*2;
    u64 acc0 = 0, acc1 = 0;
    for (int o = os; o < oe; o++) {
        float2 w = *(const float2*)&g_w3T[o*DIM + d];
        u64 g2 = *(const u64*)&gs[o];
        acc0 = fma2(g2, pk2(w.x, w.x), acc0);
        acc1 = fma2(g2, pk2(w.y, w.y), acc1);
    }
    if (oh) { part[p][oh-1][0] = acc0; part[p][oh-1][1] = acc1; }
    __syncthreads();
    if (oh == 0) {
        #pragma unroll
        for (int m = 0; m < 3; m++) {
            acc0 = add2(acc0, part[p][m][0]);
            acc1 = add2(acc1, part[p][m][1]);
        }
        float2 A = up2(acc0), B = up2(acc1);
        float2 bb = *(const float2*)&b3[d];
        out[i0*DIM + d]       = g_resid[i0*DIM + d]       + A.x + bb.x;
        out[(i0+1)*DIM + d]   = g_resid[(i0+1)*DIM + d]   + A.y + bb.x;
        out[i0*DIM + d+1]     = g_resid[i0*DIM + d+1]     + B.x + bb.y;
        out[(i0+1)*DIM + d+1] = g_resid[(i0+1)*DIM + d+1] + B.y + bb.y;
    }
}

// ---------------- launch ----------------
extern "C" void kernel_launch(void* const* d_in, const int* in_sizes, int n_in,
                              void* d_out, int out_size) {
    const float* x      = (const float*)d_in[0];
    const float* coords = (const float*)d_in[1];
    const float* ln1_w  = (const float*)d_in[2];
    const float* ln1_b  = (const float*)d_in[3];
    const float* ln2_w  = (const float*)d_in[4];
    const float* ln2_b  = (const float*)d_in[5];
    const float* qkv_w  = (const float*)d_in[6];
    const float* qkv_b  = (const float*)d_in[7];
    const float* rb1_w  = (const float*)d_in[8];
    const float* rb1_b  = (const float*)d_in[9];
    const float* rb2_w  = (const float*)d_in[10];
    const float* rb2_b  = (const float*)d_in[11];
    const float* rv1_w  = (const float*)d_in[12];
    const float* rv1_b  = (const float*)d_in[13];
    const float* rv2_w  = (const float*)d_in[14];
    const float* rv2_b  = (const float*)d_in[15];
    const float* w1     = (const float*)d_in[16];
    const float* b1     = (const float*)d_in[17];
    const float* w2     = (const float*)d_in[18];
    const float* b2     = (const float*)d_in[19];
    const float* w3     = (const float*)d_in[20];
    const float* b3     = (const float*)d_in[21];
    float* out = (float*)d_out;

    setup_kernel<<<1232, 256>>>(coords, rb1_w, rv1_w, rb2_w, rv2_w, qkv_w, w1, w2, w3);
    qkv_kernel<<<dim3(128, 3), 512>>>(x, ln1_w, ln1_b, qkv_b);
    scores_kernel<<<256, 512>>>(rb1_b, rb2_b);
    attn_kernel<<<256, 512>>>(x, rv1_b, rv2_b);
    ffn1_kernel<<<dim3(128, 3), 512>>>(ln2_w, ln2_b, b1, b2);
    ffn2_kernel<<<256, 512>>>(b3, out);
}